// round 5
// baseline (speedup 1.0000x reference)
#include <cuda_runtime.h>
#include <cuda_bf16.h>
#include <cstdint>

// Problem dims (fixed by the reference)
#define B_      4
#define S_      2048
#define D_      4096
#define O_      4096
#define M_      8192
#define TOPK_   2048
#define NMASKS_ 100

// ---------------------------------------------------------------------------
// Static device scratch (no runtime allocation allowed)
// ---------------------------------------------------------------------------
__device__ float g_f[D_];
__device__ float g_mask[D_];
__device__ __align__(16) __nv_bfloat16 g_xhi[(size_t)M_ * D_];
__device__ __align__(16) __nv_bfloat16 g_xlo[(size_t)M_ * D_];
__device__ __align__(16) __nv_bfloat16 g_whi[(size_t)O_ * D_];
__device__ __align__(16) __nv_bfloat16 g_wlo[(size_t)O_ * D_];

// ---------------------------------------------------------------------------
// K1: f[d] = mean over rows 0..pb of x[0, :, d]
// ---------------------------------------------------------------------------
__global__ void mean_kernel(const float* __restrict__ x, const int* __restrict__ pb)
{
    int d = blockIdx.x * blockDim.x + threadIdx.x;
    int rows = pb[0] + 1;
    float s = 0.f;
    int r = 0;
    for (; r + 4 <= rows; r += 4) {
        s += x[(size_t)(r + 0) * D_ + d];
        s += x[(size_t)(r + 1) * D_ + d];
        s += x[(size_t)(r + 2) * D_ + d];
        s += x[(size_t)(r + 3) * D_ + d];
    }
    for (; r < rows; ++r) s += x[(size_t)r * D_ + d];
    g_f[d] = s / (float)rows;
}

// ---------------------------------------------------------------------------
// K2: top-k + permutation scatter + overlap/gate -> g_mask (single block)
// ---------------------------------------------------------------------------
__global__ void select_kernel(const int* __restrict__ perm,
                              const unsigned char* __restrict__ stored)
{
    __shared__ unsigned int keys[D_];
    __shared__ unsigned char amask[D_];
    __shared__ int counts[NMASKS_];
    __shared__ int s_best[2];

    const int t = threadIdx.x;

    for (int j = t; j < D_; j += 1024) {
        keys[j]  = __float_as_uint(fabsf(g_f[j]));
        amask[j] = 0;
    }
    __syncthreads();

    for (int j = t; j < D_; j += 1024) {
        const unsigned int kj = keys[j];
        int rank = 0;
        #pragma unroll 8
        for (int i = 0; i < D_; ++i) {
            unsigned int ki = keys[i];
            rank += (ki > kj) || (ki == kj && i < j);
        }
        if (rank < TOPK_) amask[perm[j]] = 1;
    }
    __syncthreads();

    const int warp = t >> 5, lane = t & 31;
    for (int m = warp; m < NMASKS_; m += 32) {
        const unsigned char* row = stored + (size_t)m * D_;
        int c = 0;
        for (int d = lane; d < D_; d += 32) c += (int)(amask[d] & row[d]);
        #pragma unroll
        for (int o = 16; o > 0; o >>= 1) c += __shfl_down_sync(0xffffffffu, c, o);
        if (lane == 0) counts[m] = c;
    }
    __syncthreads();

    if (t == 0) {
        int best = -1, bi = 0;
        for (int m = 0; m < NMASKS_; ++m)
            if (counts[m] > best) { best = counts[m]; bi = m; }
        s_best[0] = best; s_best[1] = bi;
    }
    __syncthreads();

    const int gate = (s_best[0] >= 1229) ? 1 : 0;   // count/2048 >= float32(0.6)
    const unsigned char* brow = stored + (size_t)s_best[1] * D_;
    for (int d = t; d < D_; d += 1024)
        g_mask[d] = (gate && brow[d]) ? 1.0f : 0.0f;
}

// ---------------------------------------------------------------------------
// K3 (merged): blocks [0, 16384)  -> split X into bf16 hi/lo
//              blocks [16384, 24576) -> Weff = W + mask*Wn, split hi/lo
// 8 elements per thread.
// ---------------------------------------------------------------------------
#define XBLKS_ ((int)(((size_t)M_ * D_ / 8) / 256))   // 16384
#define WBLKS_ ((int)(((size_t)O_ * D_ / 8) / 256))   // 8192

__global__ void split_kernel(const float* __restrict__ x,
                             const float* __restrict__ w,
                             const float* __restrict__ wn)
{
    if (blockIdx.x < XBLKS_) {
        size_t i = ((size_t)blockIdx.x * 256 + threadIdx.x) * 8;
        float4 v0 = *(const float4*)(x + i);
        float4 v1 = *(const float4*)(x + i + 4);
        float v[8] = {v0.x, v0.y, v0.z, v0.w, v1.x, v1.y, v1.z, v1.w};
        __align__(16) __nv_bfloat16 h[8], l[8];
        #pragma unroll
        for (int j = 0; j < 8; ++j) {
            h[j] = __float2bfloat16(v[j]);
            l[j] = __float2bfloat16(v[j] - __bfloat162float(h[j]));
        }
        *(uint4*)(g_xhi + i) = *(uint4*)h;
        *(uint4*)(g_xlo + i) = *(uint4*)l;
    } else {
        size_t i = ((size_t)(blockIdx.x - XBLKS_) * 256 + threadIdx.x) * 8;
        const int dbase = (int)(i & (size_t)(D_ - 1));
        float4 w0 = *(const float4*)(w + i);
        float4 w1 = *(const float4*)(w + i + 4);
        float4 n0 = *(const float4*)(wn + i);
        float4 n1 = *(const float4*)(wn + i + 4);
        float wv[8] = {w0.x, w0.y, w0.z, w0.w, w1.x, w1.y, w1.z, w1.w};
        float nv[8] = {n0.x, n0.y, n0.z, n0.w, n1.x, n1.y, n1.z, n1.w};
        __align__(16) __nv_bfloat16 h[8], l[8];
        #pragma unroll
        for (int j = 0; j < 8; ++j) {
            float v = fmaf(g_mask[dbase + j], nv[j], wv[j]);
            h[j] = __float2bfloat16(v);
            l[j] = __float2bfloat16(v - __bfloat162float(h[j]));
        }
        *(uint4*)(g_whi + i) = *(uint4*)h;
        *(uint4*)(g_wlo + i) = *(uint4*)l;
    }
}

// ---------------------------------------------------------------------------
// K4: bf16x3 GEMM via mma.sync (HMMA)  C[M,N] = X[M,K] * Weff[N,K]^T
//     128x128 CTA tile, 8 warps of 64x32, K-chunk 32, cp.async double buffer.
//     2 CTAs/SM for issue-latency hiding.
// ---------------------------------------------------------------------------
#define KC        32
#define NITER     (D_ / KC)      // 128
#define TSTRIDE   80             // bytes per smem row (32 bf16 + 8 pad), 16B aligned
#define TILE_B    (128 * TSTRIDE)        // 10240
#define T_AHI     0
#define T_ALO     (1 * TILE_B)
#define T_BHI     (2 * TILE_B)
#define T_BLO     (3 * TILE_B)
#define STAGE_B   (4 * TILE_B)           // 40960
#define SMEM_GEMM (2 * STAGE_B)          // 81920  (x2 CTAs = 160KB <= 228KB)

__device__ __forceinline__ void ldsm_x4(uint32_t* r, uint32_t addr)
{
    asm volatile("ldmatrix.sync.aligned.m8n8.x4.shared.b16 {%0,%1,%2,%3}, [%4];"
                 : "=r"(r[0]), "=r"(r[1]), "=r"(r[2]), "=r"(r[3]) : "r"(addr));
}

__device__ __forceinline__ void mma16816(float* d, const uint32_t* a, const uint32_t* b)
{
    asm volatile("mma.sync.aligned.m16n8k16.row.col.f32.bf16.bf16.f32 "
                 "{%0,%1,%2,%3}, {%4,%5,%6,%7}, {%8,%9}, {%0,%1,%2,%3};"
                 : "+f"(d[0]), "+f"(d[1]), "+f"(d[2]), "+f"(d[3])
                 : "r"(a[0]), "r"(a[1]), "r"(a[2]), "r"(a[3]), "r"(b[0]), "r"(b[1]));
}

__device__ __forceinline__ void cp16(uint32_t dst, const void* src)
{
    asm volatile("cp.async.cg.shared.global [%0], [%1], 16;" :: "r"(dst), "l"(src));
}

__device__ __forceinline__ void stage_tile(uint32_t sdst, const __nv_bfloat16* __restrict__ src,
                                           int row0, int k0)
{
    const int tid = threadIdx.x;
    #pragma unroll
    for (int j = 0; j < 2; ++j) {
        int c   = tid + j * 256;        // 0..511
        int row = c >> 2;
        int col = c & 3;                // 16B chunk within 64B row payload
        cp16(sdst + row * TSTRIDE + col * 16,
             src + (size_t)(row0 + row) * D_ + k0 + col * 8);
    }
}

__device__ __forceinline__ void stage_all(uint32_t st, int bm, int bn, int k0)
{
    stage_tile(st + T_AHI, g_xhi, bm, k0);
    stage_tile(st + T_ALO, g_xlo, bm, k0);
    stage_tile(st + T_BHI, g_whi, bn, k0);
    stage_tile(st + T_BLO, g_wlo, bn, k0);
    asm volatile("cp.async.commit_group;" ::: "memory");
}

__global__ __launch_bounds__(256, 2) void gemm_kernel(float* __restrict__ C)
{
    extern __shared__ char smem[];
    uint32_t sbase;
    asm("{ .reg .u64 t; cvta.to.shared.u64 t, %1; cvt.u32.u64 %0, t; }"
        : "=r"(sbase) : "l"(smem));

    const int tid  = threadIdx.x;
    const int wid  = tid >> 5;
    const int lane = tid & 31;
    const int wm   = wid & 1;          // 2 warps along M
    const int wn   = wid >> 1;         // 4 warps along N
    const int bm   = blockIdx.y * 128;
    const int bn   = blockIdx.x * 128;

    float acc[4][4][4];
    #pragma unroll
    for (int i = 0; i < 4; ++i)
        #pragma unroll
        for (int j = 0; j < 4; ++j)
            #pragma unroll
            for (int e = 0; e < 4; ++e) acc[i][j][e] = 0.f;

    // lane addressing for ldmatrix (same formula for A and B tiles)
    const uint32_t lrow  = (uint32_t)(lane & 15);
    const uint32_t lkoff = (uint32_t)((lane >> 4) * 16);   // bytes: 8 bf16 half

    stage_all(sbase, bm, bn, 0);       // prologue: stage 0

    for (int it = 0; it < NITER; ++it) {
        const uint32_t st = sbase + (uint32_t)(it & 1) * STAGE_B;

        if (it + 1 < NITER) {
            stage_all(sbase + (uint32_t)((it + 1) & 1) * STAGE_B, bm, bn, (it + 1) * KC);
            asm volatile("cp.async.wait_group 1;" ::: "memory");
        } else {
            asm volatile("cp.async.wait_group 0;" ::: "memory");
        }
        __syncthreads();

        #pragma unroll
        for (int kk = 0; kk < KC; kk += 16) {
            const uint32_t kb = (uint32_t)(kk * 2) + lkoff;

            // B fragments first (16 regs), then stream A rows (8 regs reused)
            uint32_t bh[4][2], bl[4][2];
            #pragma unroll
            for (int g = 0; g < 2; ++g) {
                const uint32_t ro = (uint32_t)(wn * 32 + g * 16) + lrow;
                uint32_t r[4];
                ldsm_x4(r, st + T_BHI + ro * TSTRIDE + kb);
                bh[2 * g][0]     = r[0]; bh[2 * g][1]     = r[2];
                bh[2 * g + 1][0] = r[1]; bh[2 * g + 1][1] = r[3];
                ldsm_x4(r, st + T_BLO + ro * TSTRIDE + kb);
                bl[2 * g][0]     = r[0]; bl[2 * g][1]     = r[2];
                bl[2 * g + 1][0] = r[1]; bl[2 * g + 1][1] = r[3];
            }

            #pragma unroll
            for (int mt = 0; mt < 4; ++mt) {
                const uint32_t ro = (uint32_t)(wm * 64 + mt * 16) + lrow;
                uint32_t ah[4], al[4];
                ldsm_x4(ah, st + T_AHI + ro * TSTRIDE + kb);
                ldsm_x4(al, st + T_ALO + ro * TSTRIDE + kb);
                #pragma unroll
                for (int nt = 0; nt < 4; ++nt) {
                    mma16816(acc[mt][nt], ah, bh[nt]);
                    mma16816(acc[mt][nt], ah, bl[nt]);
                    mma16816(acc[mt][nt], al, bh[nt]);
                }
            }
        }
        __syncthreads();
    }

    // Epilogue: direct float2 stores
    const int er = lane >> 2;
    const int ec = (lane & 3) * 2;
    #pragma unroll
    for (int mt = 0; mt < 4; ++mt) {
        const int row = bm + wm * 64 + mt * 16 + er;
        #pragma unroll
        for (int nt = 0; nt < 4; ++nt) {
            const int col = bn + wn * 32 + nt * 8 + ec;
            *(float2*)(C + (size_t)row * O_ + col) =
                make_float2(acc[mt][nt][0], acc[mt][nt][1]);
            *(float2*)(C + (size_t)(row + 8) * O_ + col) =
                make_float2(acc[mt][nt][2], acc[mt][nt][3]);
        }
    }
}

// ---------------------------------------------------------------------------
extern "C" void kernel_launch(void* const* d_in, const int* in_sizes, int n_in,
                              void* d_out, int out_size)
{
    const float*         x      = (const float*)d_in[0];
    const float*         w      = (const float*)d_in[1];
    const float*         wn     = (const float*)d_in[2];
    const int*           perm   = (const int*)d_in[3];
    const unsigned char* stored = (const unsigned char*)d_in[4];
    const int*           pb     = (const int*)d_in[5];
    float*               out    = (float*)d_out;

    (void)in_sizes; (void)n_in; (void)out_size;

    static bool attr_set = false;
    if (!attr_set) {
        cudaFuncSetAttribute(gemm_kernel, cudaFuncAttributeMaxDynamicSharedMemorySize,
                             SMEM_GEMM);
        attr_set = true;
    }

    mean_kernel<<<D_ / 256, 256>>>(x, pb);
    select_kernel<<<1, 1024>>>(perm, stored);
    split_kernel<<<XBLKS_ + WBLKS_, 256>>>(x, w, wn);   // 24576 blocks

    dim3 grid(O_ / 128, M_ / 128);   // (32, 64)
    gemm_kernel<<<grid, 256, SMEM_GEMM>>>(out);
}

// round 6
// speedup vs baseline: 1.3389x; 1.3389x over previous
#include <cuda_runtime.h>
#include <cuda_bf16.h>
#include <cuda_fp16.h>
#include <cstdint>

// Problem dims (fixed by the reference)
#define B_      4
#define S_      2048
#define D_      4096
#define O_      4096
#define M_      8192
#define TOPK_   2048
#define NMASKS_ 100

// ---------------------------------------------------------------------------
// Static device scratch (no runtime allocation allowed)
// ---------------------------------------------------------------------------
__device__ float g_f[D_];
__device__ float g_mask[D_];
__device__ __align__(16) __half g_xh[(size_t)M_ * D_];   // fp16(x)
__device__ __align__(16) __half g_wh[(size_t)O_ * D_];   // fp16(weff)
__device__ __align__(16) __half g_wl[(size_t)O_ * D_];   // fp16(weff - wh)

// ---------------------------------------------------------------------------
// K1: f[d] = mean over rows 0..pb of x[0, :, d]
// ---------------------------------------------------------------------------
__global__ void mean_kernel(const float* __restrict__ x, const int* __restrict__ pb)
{
    int d = blockIdx.x * blockDim.x + threadIdx.x;
    int rows = pb[0] + 1;
    float s = 0.f;
    int r = 0;
    for (; r + 4 <= rows; r += 4) {
        s += x[(size_t)(r + 0) * D_ + d];
        s += x[(size_t)(r + 1) * D_ + d];
        s += x[(size_t)(r + 2) * D_ + d];
        s += x[(size_t)(r + 3) * D_ + d];
    }
    for (; r < rows; ++r) s += x[(size_t)r * D_ + d];
    g_f[d] = s / (float)rows;
}

// ---------------------------------------------------------------------------
// K2: top-k + permutation scatter + overlap/gate -> g_mask (single block)
// ---------------------------------------------------------------------------
__global__ void select_kernel(const int* __restrict__ perm,
                              const unsigned char* __restrict__ stored)
{
    __shared__ unsigned int keys[D_];
    __shared__ unsigned char amask[D_];
    __shared__ int counts[NMASKS_];
    __shared__ int s_best[2];

    const int t = threadIdx.x;

    for (int j = t; j < D_; j += 1024) {
        keys[j]  = __float_as_uint(fabsf(g_f[j]));
        amask[j] = 0;
    }
    __syncthreads();

    for (int j = t; j < D_; j += 1024) {
        const unsigned int kj = keys[j];
        int rank = 0;
        #pragma unroll 8
        for (int i = 0; i < D_; ++i) {
            unsigned int ki = keys[i];
            rank += (ki > kj) || (ki == kj && i < j);
        }
        if (rank < TOPK_) amask[perm[j]] = 1;
    }
    __syncthreads();

    const int warp = t >> 5, lane = t & 31;
    for (int m = warp; m < NMASKS_; m += 32) {
        const unsigned char* row = stored + (size_t)m * D_;
        int c = 0;
        for (int d = lane; d < D_; d += 32) c += (int)(amask[d] & row[d]);
        #pragma unroll
        for (int o = 16; o > 0; o >>= 1) c += __shfl_down_sync(0xffffffffu, c, o);
        if (lane == 0) counts[m] = c;
    }
    __syncthreads();

    if (t == 0) {
        int best = -1, bi = 0;
        for (int m = 0; m < NMASKS_; ++m)
            if (counts[m] > best) { best = counts[m]; bi = m; }
        s_best[0] = best; s_best[1] = bi;
    }
    __syncthreads();

    const int gate = (s_best[0] >= 1229) ? 1 : 0;   // count/2048 >= float32(0.6)
    const unsigned char* brow = stored + (size_t)s_best[1] * D_;
    for (int d = t; d < D_; d += 1024)
        g_mask[d] = (gate && brow[d]) ? 1.0f : 0.0f;
}

// ---------------------------------------------------------------------------
// K3 (merged): blocks [0, 16384)      -> x -> fp16
//              blocks [16384, 24576)  -> weff = w + mask*wn -> fp16 hi/lo
// 8 elements per thread.
// ---------------------------------------------------------------------------
#define XBLKS_ ((int)(((size_t)M_ * D_ / 8) / 256))   // 16384
#define WBLKS_ ((int)(((size_t)O_ * D_ / 8) / 256))   // 8192

__global__ void split_kernel(const float* __restrict__ x,
                             const float* __restrict__ w,
                             const float* __restrict__ wn)
{
    if (blockIdx.x < XBLKS_) {
        size_t i = ((size_t)blockIdx.x * 256 + threadIdx.x) * 8;
        float4 v0 = *(const float4*)(x + i);
        float4 v1 = *(const float4*)(x + i + 4);
        float v[8] = {v0.x, v0.y, v0.z, v0.w, v1.x, v1.y, v1.z, v1.w};
        __align__(16) __half h[8];
        #pragma unroll
        for (int j = 0; j < 8; ++j) h[j] = __float2half(v[j]);
        *(uint4*)(g_xh + i) = *(uint4*)h;
    } else {
        size_t i = ((size_t)(blockIdx.x - XBLKS_) * 256 + threadIdx.x) * 8;
        const int dbase = (int)(i & (size_t)(D_ - 1));
        float4 w0 = *(const float4*)(w + i);
        float4 w1 = *(const float4*)(w + i + 4);
        float4 n0 = *(const float4*)(wn + i);
        float4 n1 = *(const float4*)(wn + i + 4);
        float wv[8] = {w0.x, w0.y, w0.z, w0.w, w1.x, w1.y, w1.z, w1.w};
        float nv[8] = {n0.x, n0.y, n0.z, n0.w, n1.x, n1.y, n1.z, n1.w};
        __align__(16) __half h[8], l[8];
        #pragma unroll
        for (int j = 0; j < 8; ++j) {
            float v = fmaf(g_mask[dbase + j], nv[j], wv[j]);
            h[j] = __float2half(v);
            l[j] = __float2half(v - __half2float(h[j]));
        }
        *(uint4*)(g_wh + i) = *(uint4*)h;
        *(uint4*)(g_wl + i) = *(uint4*)l;
    }
}

// ---------------------------------------------------------------------------
// K4: fp16 asymmetric-split GEMM via mma.sync (HMMA)
//     C[M,N] = Xfp16[M,K] * (Wh + Wl)[N,K]^T, fp32 accumulate
//     128x128 CTA tile, 8 warps of 64x32, KC=32, 3-stage cp.async pipeline,
//     2 CTAs/SM.
// ---------------------------------------------------------------------------
#define KC        32
#define NITER     (D_ / KC)              // 128
#define TSTRIDE   80                     // 64B payload + 16B pad
#define TILE_B    (128 * TSTRIDE)        // 10240
#define T_A       0
#define T_BH      (1 * TILE_B)
#define T_BL      (2 * TILE_B)
#define STAGE_B   (3 * TILE_B)           // 30720
#define NSTAGE    3
#define SMEM_GEMM (NSTAGE * STAGE_B)     // 92160 (x2 CTAs = 184KB <= 228KB)

__device__ __forceinline__ void ldsm_x4(uint32_t* r, uint32_t addr)
{
    asm volatile("ldmatrix.sync.aligned.m8n8.x4.shared.b16 {%0,%1,%2,%3}, [%4];"
                 : "=r"(r[0]), "=r"(r[1]), "=r"(r[2]), "=r"(r[3]) : "r"(addr));
}

__device__ __forceinline__ void mma16816(float* d, const uint32_t* a, const uint32_t* b)
{
    asm volatile("mma.sync.aligned.m16n8k16.row.col.f32.f16.f16.f32 "
                 "{%0,%1,%2,%3}, {%4,%5,%6,%7}, {%8,%9}, {%0,%1,%2,%3};"
                 : "+f"(d[0]), "+f"(d[1]), "+f"(d[2]), "+f"(d[3])
                 : "r"(a[0]), "r"(a[1]), "r"(a[2]), "r"(a[3]), "r"(b[0]), "r"(b[1]));
}

__device__ __forceinline__ void cp16(uint32_t dst, const void* src)
{
    asm volatile("cp.async.cg.shared.global [%0], [%1], 16;" :: "r"(dst), "l"(src));
}

__device__ __forceinline__ void stage_tile(uint32_t sdst, const __half* __restrict__ src,
                                           int row0, int k0)
{
    const int tid = threadIdx.x;
    #pragma unroll
    for (int j = 0; j < 2; ++j) {
        int c   = tid + j * 256;        // 0..511
        int row = c >> 2;
        int col = c & 3;                // 16B chunk within 64B row payload
        cp16(sdst + row * TSTRIDE + col * 16,
             src + (size_t)(row0 + row) * D_ + k0 + col * 8);
    }
}

__device__ __forceinline__ void stage_all(uint32_t st, int bm, int bn, int k0)
{
    stage_tile(st + T_A,  g_xh, bm, k0);
    stage_tile(st + T_BH, g_wh, bn, k0);
    stage_tile(st + T_BL, g_wl, bn, k0);
    asm volatile("cp.async.commit_group;" ::: "memory");
}

__global__ __launch_bounds__(256, 2) void gemm_kernel(float* __restrict__ C)
{
    extern __shared__ char smem[];
    uint32_t sbase;
    asm("{ .reg .u64 t; cvta.to.shared.u64 t, %1; cvt.u32.u64 %0, t; }"
        : "=r"(sbase) : "l"(smem));

    const int tid  = threadIdx.x;
    const int wid  = tid >> 5;
    const int lane = tid & 31;
    const int wm   = wid & 1;          // 2 warps along M
    const int wn   = wid >> 1;         // 4 warps along N
    const int bm   = blockIdx.y * 128;
    const int bn   = blockIdx.x * 128;

    float acc[4][4][4];
    #pragma unroll
    for (int i = 0; i < 4; ++i)
        #pragma unroll
        for (int j = 0; j < 4; ++j)
            #pragma unroll
            for (int e = 0; e < 4; ++e) acc[i][j][e] = 0.f;

    const uint32_t lrow  = (uint32_t)(lane & 15);
    const uint32_t lkoff = (uint32_t)((lane >> 4) * 16);

    // prologue: stages 0, 1
    stage_all(sbase + 0 * STAGE_B, bm, bn, 0);
    stage_all(sbase + 1 * STAGE_B, bm, bn, KC);

    uint32_t st = sbase;
    int snext = 2;                      // next stage slot to fill

    for (int it = 0; it < NITER; ++it) {
        asm volatile("cp.async.wait_group 1;" ::: "memory");
        __syncthreads();

        // refill the slot freed at the previous iteration
        if (it + 2 < NITER) {
            stage_all(sbase + (uint32_t)snext * STAGE_B, bm, bn, (it + 2) * KC);
        } else {
            asm volatile("cp.async.commit_group;" ::: "memory");
        }
        if (++snext == NSTAGE) snext = 0;

        #pragma unroll
        for (int kk = 0; kk < 2; ++kk) {
            const uint32_t kb = (uint32_t)(kk * 32) + lkoff;

            uint32_t bh[4][2], bl[4][2];
            #pragma unroll
            for (int g = 0; g < 2; ++g) {
                const uint32_t ro = (uint32_t)(wn * 32 + g * 16) + lrow;
                uint32_t r[4];
                ldsm_x4(r, st + T_BH + ro * TSTRIDE + kb);
                bh[2 * g][0]     = r[0]; bh[2 * g][1]     = r[2];
                bh[2 * g + 1][0] = r[1]; bh[2 * g + 1][1] = r[3];
                ldsm_x4(r, st + T_BL + ro * TSTRIDE + kb);
                bl[2 * g][0]     = r[0]; bl[2 * g][1]     = r[2];
                bl[2 * g + 1][0] = r[1]; bl[2 * g + 1][1] = r[3];
            }

            #pragma unroll
            for (int mt = 0; mt < 4; ++mt) {
                const uint32_t ro = (uint32_t)(wm * 64 + mt * 16) + lrow;
                uint32_t a[4];
                ldsm_x4(a, st + T_A + ro * TSTRIDE + kb);
                #pragma unroll
                for (int nt = 0; nt < 4; ++nt) {
                    mma16816(acc[mt][nt], a, bh[nt]);
                    mma16816(acc[mt][nt], a, bl[nt]);
                }
            }
        }

        st += STAGE_B;
        if (st == sbase + NSTAGE * STAGE_B) st = sbase;
    }

    // Epilogue: direct float2 stores
    const int er = lane >> 2;
    const int ec = (lane & 3) * 2;
    #pragma unroll
    for (int mt = 0; mt < 4; ++mt) {
        const int row = bm + wm * 64 + mt * 16 + er;
        #pragma unroll
        for (int nt = 0; nt < 4; ++nt) {
            const int col = bn + wn * 32 + nt * 8 + ec;
            *(float2*)(C + (size_t)row * O_ + col) =
                make_float2(acc[mt][nt][0], acc[mt][nt][1]);
            *(float2*)(C + (size_t)(row + 8) * O_ + col) =
                make_float2(acc[mt][nt][2], acc[mt][nt][3]);
        }
    }
}

// ---------------------------------------------------------------------------
extern "C" void kernel_launch(void* const* d_in, const int* in_sizes, int n_in,
                              void* d_out, int out_size)
{
    const float*         x      = (const float*)d_in[0];
    const float*         w      = (const float*)d_in[1];
    const float*         wn     = (const float*)d_in[2];
    const int*           perm   = (const int*)d_in[3];
    const unsigned char* stored = (const unsigned char*)d_in[4];
    const int*           pb     = (const int*)d_in[5];
    float*               out    = (float*)d_out;

    (void)in_sizes; (void)n_in; (void)out_size;

    static bool attr_set = false;
    if (!attr_set) {
        cudaFuncSetAttribute(gemm_kernel, cudaFuncAttributeMaxDynamicSharedMemorySize,
                             SMEM_GEMM);
        attr_set = true;
    }

    mean_kernel<<<D_ / 256, 256>>>(x, pb);
    select_kernel<<<1, 1024>>>(perm, stored);
    split_kernel<<<XBLKS_ + WBLKS_, 256>>>(x, w, wn);   // 24576 blocks

    dim3 grid(O_ / 128, M_ / 128);   // (32, 64)
    gemm_kernel<<<grid, 256, SMEM_GEMM>>>(out);
}

// round 7
// speedup vs baseline: 1.9779x; 1.4773x over previous
#include <cuda_runtime.h>
#include <cuda_bf16.h>
#include <cuda_fp16.h>
#include <cstdint>

// Problem dims (fixed by the reference)
#define B_      4
#define S_      2048
#define D_      4096
#define O_      4096
#define M_      8192
#define TOPK_   2048
#define NMASKS_ 100

// ---------------------------------------------------------------------------
// Static device scratch (no runtime allocation allowed)
// ---------------------------------------------------------------------------
__device__ float g_f[D_];
__device__ float g_mask[D_];
__device__ __align__(16) __half g_xh[(size_t)M_ * D_];   // fp16(x)
__device__ __align__(16) __half g_wh[(size_t)O_ * D_];   // fp16(weff)

// ---------------------------------------------------------------------------
// K1: f[d] = mean over rows 0..pb of x[0, :, d]
// ---------------------------------------------------------------------------
__global__ void mean_kernel(const float* __restrict__ x, const int* __restrict__ pb)
{
    int d = blockIdx.x * blockDim.x + threadIdx.x;
    int rows = pb[0] + 1;
    float s = 0.f;
    int r = 0;
    for (; r + 4 <= rows; r += 4) {
        s += x[(size_t)(r + 0) * D_ + d];
        s += x[(size_t)(r + 1) * D_ + d];
        s += x[(size_t)(r + 2) * D_ + d];
        s += x[(size_t)(r + 3) * D_ + d];
    }
    for (; r < rows; ++r) s += x[(size_t)r * D_ + d];
    g_f[d] = s / (float)rows;
}

// ---------------------------------------------------------------------------
// K2: top-k + permutation scatter + overlap/gate -> g_mask (single block)
// ---------------------------------------------------------------------------
__global__ void select_kernel(const int* __restrict__ perm,
                              const unsigned char* __restrict__ stored)
{
    __shared__ unsigned int keys[D_];
    __shared__ unsigned char amask[D_];
    __shared__ int counts[NMASKS_];
    __shared__ int s_best[2];

    const int t = threadIdx.x;

    for (int j = t; j < D_; j += 1024) {
        keys[j]  = __float_as_uint(fabsf(g_f[j]));
        amask[j] = 0;
    }
    __syncthreads();

    for (int j = t; j < D_; j += 1024) {
        const unsigned int kj = keys[j];
        int rank = 0;
        #pragma unroll 8
        for (int i = 0; i < D_; ++i) {
            unsigned int ki = keys[i];
            rank += (ki > kj) || (ki == kj && i < j);
        }
        if (rank < TOPK_) amask[perm[j]] = 1;
    }
    __syncthreads();

    const int warp = t >> 5, lane = t & 31;
    for (int m = warp; m < NMASKS_; m += 32) {
        const unsigned char* row = stored + (size_t)m * D_;
        int c = 0;
        for (int d = lane; d < D_; d += 32) c += (int)(amask[d] & row[d]);
        #pragma unroll
        for (int o = 16; o > 0; o >>= 1) c += __shfl_down_sync(0xffffffffu, c, o);
        if (lane == 0) counts[m] = c;
    }
    __syncthreads();

    if (t == 0) {
        int best = -1, bi = 0;
        for (int m = 0; m < NMASKS_; ++m)
            if (counts[m] > best) { best = counts[m]; bi = m; }
        s_best[0] = best; s_best[1] = bi;
    }
    __syncthreads();

    const int gate = (s_best[0] >= 1229) ? 1 : 0;   // count/2048 >= float32(0.6)
    const unsigned char* brow = stored + (size_t)s_best[1] * D_;
    for (int d = t; d < D_; d += 1024)
        g_mask[d] = (gate && brow[d]) ? 1.0f : 0.0f;
}

// ---------------------------------------------------------------------------
// K3 (merged): blocks [0, 16384)      -> x -> fp16
//              blocks [16384, 24576)  -> weff = w + mask*wn -> fp16
// 8 elements per thread.
// ---------------------------------------------------------------------------
#define XBLKS_ ((int)(((size_t)M_ * D_ / 8) / 256))   // 16384
#define WBLKS_ ((int)(((size_t)O_ * D_ / 8) / 256))   // 8192

__global__ void split_kernel(const float* __restrict__ x,
                             const float* __restrict__ w,
                             const float* __restrict__ wn)
{
    if (blockIdx.x < XBLKS_) {
        size_t i = ((size_t)blockIdx.x * 256 + threadIdx.x) * 8;
        float4 v0 = *(const float4*)(x + i);
        float4 v1 = *(const float4*)(x + i + 4);
        float v[8] = {v0.x, v0.y, v0.z, v0.w, v1.x, v1.y, v1.z, v1.w};
        __align__(16) __half h[8];
        #pragma unroll
        for (int j = 0; j < 8; ++j) h[j] = __float2half(v[j]);
        *(uint4*)(g_xh + i) = *(uint4*)h;
    } else {
        size_t i = ((size_t)(blockIdx.x - XBLKS_) * 256 + threadIdx.x) * 8;
        const int dbase = (int)(i & (size_t)(D_ - 1));
        float4 w0 = *(const float4*)(w + i);
        float4 w1 = *(const float4*)(w + i + 4);
        float4 n0 = *(const float4*)(wn + i);
        float4 n1 = *(const float4*)(wn + i + 4);
        float wv[8] = {w0.x, w0.y, w0.z, w0.w, w1.x, w1.y, w1.z, w1.w};
        float nv[8] = {n0.x, n0.y, n0.z, n0.w, n1.x, n1.y, n1.z, n1.w};
        __align__(16) __half h[8];
        #pragma unroll
        for (int j = 0; j < 8; ++j)
            h[j] = __float2half(fmaf(g_mask[dbase + j], nv[j], wv[j]));
        *(uint4*)(g_wh + i) = *(uint4*)h;
    }
}

// ---------------------------------------------------------------------------
// K4: fp16 GEMM via mma.sync (HMMA), fp32 accumulate
//     C[M,N] = Xfp16[M,K] * Wfp16[N,K]^T
//     128x128 CTA tile, 8 warps of 64x32, KC=32, 4-stage cp.async pipeline,
//     2 CTAs/SM.
// ---------------------------------------------------------------------------
#define KC        32
#define NITER     (D_ / KC)              // 128
#define TSTRIDE   80                     // 64B payload + 16B pad
#define TILE_B    (128 * TSTRIDE)        // 10240
#define T_A       0
#define T_BH      (1 * TILE_B)
#define STAGE_B   (2 * TILE_B)           // 20480
#define NSTAGE    4
#define SMEM_GEMM (NSTAGE * STAGE_B)     // 81920 (x2 CTAs = 160KB <= 228KB)

__device__ __forceinline__ void ldsm_x4(uint32_t* r, uint32_t addr)
{
    asm volatile("ldmatrix.sync.aligned.m8n8.x4.shared.b16 {%0,%1,%2,%3}, [%4];"
                 : "=r"(r[0]), "=r"(r[1]), "=r"(r[2]), "=r"(r[3]) : "r"(addr));
}

__device__ __forceinline__ void mma16816(float* d, const uint32_t* a, const uint32_t* b)
{
    asm volatile("mma.sync.aligned.m16n8k16.row.col.f32.f16.f16.f32 "
                 "{%0,%1,%2,%3}, {%4,%5,%6,%7}, {%8,%9}, {%0,%1,%2,%3};"
                 : "+f"(d[0]), "+f"(d[1]), "+f"(d[2]), "+f"(d[3])
                 : "r"(a[0]), "r"(a[1]), "r"(a[2]), "r"(a[3]), "r"(b[0]), "r"(b[1]));
}

__device__ __forceinline__ void cp16(uint32_t dst, const void* src)
{
    asm volatile("cp.async.cg.shared.global [%0], [%1], 16;" :: "r"(dst), "l"(src));
}

__device__ __forceinline__ void stage_tile(uint32_t sdst, const __half* __restrict__ src,
                                           int row0, int k0)
{
    const int tid = threadIdx.x;
    #pragma unroll
    for (int j = 0; j < 2; ++j) {
        int c   = tid + j * 256;        // 0..511
        int row = c >> 2;
        int col = c & 3;                // 16B chunk within 64B row payload
        cp16(sdst + row * TSTRIDE + col * 16,
             src + (size_t)(row0 + row) * D_ + k0 + col * 8);
    }
}

__device__ __forceinline__ void stage_all(uint32_t st, int bm, int bn, int k0)
{
    stage_tile(st + T_A,  g_xh, bm, k0);
    stage_tile(st + T_BH, g_wh, bn, k0);
    asm volatile("cp.async.commit_group;" ::: "memory");
}

__global__ __launch_bounds__(256, 2) void gemm_kernel(float* __restrict__ C)
{
    extern __shared__ char smem[];
    uint32_t sbase;
    asm("{ .reg .u64 t; cvta.to.shared.u64 t, %1; cvt.u32.u64 %0, t; }"
        : "=r"(sbase) : "l"(smem));

    const int tid  = threadIdx.x;
    const int wid  = tid >> 5;
    const int lane = tid & 31;
    const int wm   = wid & 1;          // 2 warps along M
    const int wn   = wid >> 1;         // 4 warps along N
    const int bm   = blockIdx.y * 128;
    const int bn   = blockIdx.x * 128;

    float acc[4][4][4];
    #pragma unroll
    for (int i = 0; i < 4; ++i)
        #pragma unroll
        for (int j = 0; j < 4; ++j)
            #pragma unroll
            for (int e = 0; e < 4; ++e) acc[i][j][e] = 0.f;

    const uint32_t lrow  = (uint32_t)(lane & 15);
    const uint32_t lkoff = (uint32_t)((lane >> 4) * 16);

    // prologue: stages 0, 1, 2
    stage_all(sbase + 0 * STAGE_B, bm, bn, 0 * KC);
    stage_all(sbase + 1 * STAGE_B, bm, bn, 1 * KC);
    stage_all(sbase + 2 * STAGE_B, bm, bn, 2 * KC);

    for (int it = 0; it < NITER; ++it) {
        const uint32_t st = sbase + (uint32_t)(it & 3) * STAGE_B;

        asm volatile("cp.async.wait_group 2;" ::: "memory");
        __syncthreads();

        // refill the slot consumed last iteration (all warps passed the sync)
        if (it + 3 < NITER) {
            stage_all(sbase + (uint32_t)((it + 3) & 3) * STAGE_B, bm, bn, (it + 3) * KC);
        } else {
            asm volatile("cp.async.commit_group;" ::: "memory");
        }

        #pragma unroll
        for (int kk = 0; kk < 2; ++kk) {
            const uint32_t kb = (uint32_t)(kk * 32) + lkoff;

            uint32_t bh[4][2];
            #pragma unroll
            for (int g = 0; g < 2; ++g) {
                const uint32_t ro = (uint32_t)(wn * 32 + g * 16) + lrow;
                uint32_t r[4];
                ldsm_x4(r, st + T_BH + ro * TSTRIDE + kb);
                bh[2 * g][0]     = r[0]; bh[2 * g][1]     = r[2];
                bh[2 * g + 1][0] = r[1]; bh[2 * g + 1][1] = r[3];
            }

            #pragma unroll
            for (int mt = 0; mt < 4; ++mt) {
                const uint32_t ro = (uint32_t)(wm * 64 + mt * 16) + lrow;
                uint32_t a[4];
                ldsm_x4(a, st + T_A + ro * TSTRIDE + kb);
                #pragma unroll
                for (int nt = 0; nt < 4; ++nt)
                    mma16816(acc[mt][nt], a, bh[nt]);
            }
        }
    }

    // Epilogue: direct float2 stores
    const int er = lane >> 2;
    const int ec = (lane & 3) * 2;
    #pragma unroll
    for (int mt = 0; mt < 4; ++mt) {
        const int row = bm + wm * 64 + mt * 16 + er;
        #pragma unroll
        for (int nt = 0; nt < 4; ++nt) {
            const int col = bn + wn * 32 + nt * 8 + ec;
            *(float2*)(C + (size_t)row * O_ + col) =
                make_float2(acc[mt][nt][0], acc[mt][nt][1]);
            *(float2*)(C + (size_t)(row + 8) * O_ + col) =
                make_float2(acc[mt][nt][2], acc[mt][nt][3]);
        }
    }
}

// ---------------------------------------------------------------------------
extern "C" void kernel_launch(void* const* d_in, const int* in_sizes, int n_in,
                              void* d_out, int out_size)
{
    const float*         x      = (const float*)d_in[0];
    const float*         w      = (const float*)d_in[1];
    const float*         wn     = (const float*)d_in[2];
    const int*           perm   = (const int*)d_in[3];
    const unsigned char* stored = (const unsigned char*)d_in[4];
    const int*           pb     = (const int*)d_in[5];
    float*               out    = (float*)d_out;

    (void)in_sizes; (void)n_in; (void)out_size;

    static bool attr_set = false;
    if (!attr_set) {
        cudaFuncSetAttribute(gemm_kernel, cudaFuncAttributeMaxDynamicSharedMemorySize,
                             SMEM_GEMM);
        attr_set = true;
    }

    mean_kernel<<<D_ / 256, 256>>>(x, pb);
    select_kernel<<<1, 1024>>>(perm, stored);
    split_kernel<<<XBLKS_ + WBLKS_, 256>>>(x, w, wn);   // 24576 blocks

    dim3 grid(O_ / 128, M_ / 128);   // (32, 64)
    gemm_kernel<<<grid, 256, SMEM_GEMM>>>(out);
}

// round 8
// speedup vs baseline: 3.1650x; 1.6001x over previous
#include <cuda_runtime.h>
#include <cuda_bf16.h>
#include <cuda_fp16.h>
#include <cstdint>

// Problem dims (fixed by the reference)
#define B_      4
#define S_      2048
#define D_      4096
#define O_      4096
#define M_      8192
#define TOPK_   2048
#define NMASKS_ 100

// ---------------------------------------------------------------------------
// Static device scratch (no runtime allocation allowed)
// ---------------------------------------------------------------------------
__device__ float g_psum[8][D_];
__device__ float g_f[D_];
__device__ unsigned char g_amask[D_];
__device__ float g_mask[D_];
__device__ __align__(16) __half g_xh[(size_t)M_ * D_];   // fp16(x)
__device__ __align__(16) __half g_wh[(size_t)O_ * D_];   // fp16(weff)

// ---------------------------------------------------------------------------
// K1a: partial column sums of x[0, 0..pb, :] over 8 row chunks
// grid (32, 8), 128 threads
// ---------------------------------------------------------------------------
__global__ void mean_p1(const float* __restrict__ x, const int* __restrict__ pb)
{
    const int d = blockIdx.x * 128 + threadIdx.x;
    const int rows  = pb[0] + 1;
    const int chunk = (rows + 7) / 8;
    const int r0 = blockIdx.y * chunk;
    const int r1 = (r0 + chunk < rows) ? (r0 + chunk) : rows;
    float s = 0.f;
    int r = r0;
    for (; r + 4 <= r1; r += 4) {
        s += x[(size_t)(r + 0) * D_ + d];
        s += x[(size_t)(r + 1) * D_ + d];
        s += x[(size_t)(r + 2) * D_ + d];
        s += x[(size_t)(r + 3) * D_ + d];
    }
    for (; r < r1; ++r) s += x[(size_t)r * D_ + d];
    g_psum[blockIdx.y][d] = s;
}

// ---------------------------------------------------------------------------
// K1b: reduce partials -> g_f; also zero the scatter mask
// grid 16, 256 threads
// ---------------------------------------------------------------------------
__global__ void mean_p2(const int* __restrict__ pb)
{
    const int d = blockIdx.x * 256 + threadIdx.x;
    const int rows = pb[0] + 1;
    float s = 0.f;
    #pragma unroll
    for (int y = 0; y < 8; ++y) s += g_psum[y][d];
    g_f[d] = s / (float)rows;
    g_amask[d] = 0;
}

// ---------------------------------------------------------------------------
// K2a: exact top-k rank by counting, 32 blocks x 512 threads.
// Block b handles j in [b*128, (b+1)*128); 4 threads per j scan 1024 i each.
// rank(j) = #{i : key_i > key_j  or (key_i == key_j and i < j)}
// ---------------------------------------------------------------------------
__global__ void rank_kernel(const int* __restrict__ perm)
{
    __shared__ unsigned int keys[D_];
    __shared__ int sr[128][4];

    const int t = threadIdx.x;
    for (int j = t; j < D_; j += 512)
        keys[j] = __float_as_uint(fabsf(g_f[j]));
    __syncthreads();

    const int jl = t & 127;
    const int h  = t >> 7;                       // 0..3
    const int j  = blockIdx.x * 128 + jl;
    const unsigned int kj = keys[j];
    int r = 0;
    const int i0 = h * 1024;
    #pragma unroll 8
    for (int i = i0; i < i0 + 1024; ++i) {
        const unsigned int ki = keys[i];
        r += (ki > kj) || (ki == kj && i < j);
    }
    sr[jl][h] = r;
    __syncthreads();

    if (t < 128) {
        const int rank = sr[t][0] + sr[t][1] + sr[t][2] + sr[t][3];
        if (rank < TOPK_)
            g_amask[perm[blockIdx.x * 128 + t]] = 1;   // perm: no conflicts
    }
}

// ---------------------------------------------------------------------------
// K2b: overlap counts, argmax, gate -> g_mask (single block, 1024 threads)
// ---------------------------------------------------------------------------
__global__ void gate_kernel(const unsigned char* __restrict__ stored)
{
    __shared__ unsigned char am[D_];
    __shared__ int counts[NMASKS_];
    __shared__ int s_best[2];

    const int t = threadIdx.x;
    for (int d = t; d < D_; d += 1024) am[d] = g_amask[d];
    __syncthreads();

    const int warp = t >> 5, lane = t & 31;
    for (int m = warp; m < NMASKS_; m += 32) {
        const unsigned char* row = stored + (size_t)m * D_;
        int c = 0;
        for (int d = lane; d < D_; d += 32) c += (int)(am[d] & row[d]);
        #pragma unroll
        for (int o = 16; o > 0; o >>= 1) c += __shfl_down_sync(0xffffffffu, c, o);
        if (lane == 0) counts[m] = c;
    }
    __syncthreads();

    if (t == 0) {
        int best = -1, bi = 0;
        for (int m = 0; m < NMASKS_; ++m)
            if (counts[m] > best) { best = counts[m]; bi = m; }   // first max
        s_best[0] = best; s_best[1] = bi;
    }
    __syncthreads();

    const int gate = (s_best[0] >= 1229) ? 1 : 0;   // count/2048 >= float32(0.6)
    const unsigned char* brow = stored + (size_t)s_best[1] * D_;
    for (int d = t; d < D_; d += 1024)
        g_mask[d] = (gate && brow[d]) ? 1.0f : 0.0f;
}

// ---------------------------------------------------------------------------
// K3 (merged): blocks [0, 16384)      -> x -> fp16
//              blocks [16384, 24576)  -> weff = w + mask*wn -> fp16
// ---------------------------------------------------------------------------
#define XBLKS_ ((int)(((size_t)M_ * D_ / 8) / 256))   // 16384
#define WBLKS_ ((int)(((size_t)O_ * D_ / 8) / 256))   // 8192

__global__ void split_kernel(const float* __restrict__ x,
                             const float* __restrict__ w,
                             const float* __restrict__ wn)
{
    if (blockIdx.x < XBLKS_) {
        size_t i = ((size_t)blockIdx.x * 256 + threadIdx.x) * 8;
        float4 v0 = *(const float4*)(x + i);
        float4 v1 = *(const float4*)(x + i + 4);
        float v[8] = {v0.x, v0.y, v0.z, v0.w, v1.x, v1.y, v1.z, v1.w};
        __align__(16) __half h[8];
        #pragma unroll
        for (int j = 0; j < 8; ++j) h[j] = __float2half(v[j]);
        *(uint4*)(g_xh + i) = *(uint4*)h;
    } else {
        size_t i = ((size_t)(blockIdx.x - XBLKS_) * 256 + threadIdx.x) * 8;
        const int dbase = (int)(i & (size_t)(D_ - 1));
        float4 w0 = *(const float4*)(w + i);
        float4 w1 = *(const float4*)(w + i + 4);
        float4 n0 = *(const float4*)(wn + i);
        float4 n1 = *(const float4*)(wn + i + 4);
        float wv[8] = {w0.x, w0.y, w0.z, w0.w, w1.x, w1.y, w1.z, w1.w};
        float nv[8] = {n0.x, n0.y, n0.z, n0.w, n1.x, n1.y, n1.z, n1.w};
        __align__(16) __half h[8];
        #pragma unroll
        for (int j = 0; j < 8; ++j)
            h[j] = __float2half(fmaf(g_mask[dbase + j], nv[j], wv[j]));
        *(uint4*)(g_wh + i) = *(uint4*)h;
    }
}

// ---------------------------------------------------------------------------
// K4: fp16 GEMM via mma.sync (HMMA), fp32 accumulate
//     C[M,N] = Xfp16[M,K] * Wfp16[N,K]^T
//     128x128 CTA tile, 8 warps of 64x32, KC=64, 2-stage cp.async pipeline,
//     2 CTAs/SM, batched fragment loads.
// ---------------------------------------------------------------------------
#define KC        64
#define NITER     (D_ / KC)              // 64
#define TSTRIDE   144                    // 128B payload + 16B pad (banks 4r mod 32)
#define TILE_B    (128 * TSTRIDE)        // 18432
#define T_A       0
#define T_B       TILE_B
#define STAGE_B   (2 * TILE_B)           // 36864
#define SMEM_GEMM (2 * STAGE_B)          // 73728 (x2 CTAs = 147KB <= 228KB)

__device__ __forceinline__ void ldsm_x4(uint32_t* r, uint32_t addr)
{
    asm volatile("ldmatrix.sync.aligned.m8n8.x4.shared.b16 {%0,%1,%2,%3}, [%4];"
                 : "=r"(r[0]), "=r"(r[1]), "=r"(r[2]), "=r"(r[3]) : "r"(addr));
}

__device__ __forceinline__ void mma16816(float* d, const uint32_t* a, const uint32_t* b)
{
    asm volatile("mma.sync.aligned.m16n8k16.row.col.f32.f16.f16.f32 "
                 "{%0,%1,%2,%3}, {%4,%5,%6,%7}, {%8,%9}, {%0,%1,%2,%3};"
                 : "+f"(d[0]), "+f"(d[1]), "+f"(d[2]), "+f"(d[3])
                 : "r"(a[0]), "r"(a[1]), "r"(a[2]), "r"(a[3]), "r"(b[0]), "r"(b[1]));
}

__device__ __forceinline__ void cp16(uint32_t dst, const void* src)
{
    asm volatile("cp.async.cg.shared.global [%0], [%1], 16;" :: "r"(dst), "l"(src));
}

__device__ __forceinline__ void stage_tile(uint32_t sdst, const __half* __restrict__ src,
                                           int row0, int k0)
{
    const int tid = threadIdx.x;
    #pragma unroll
    for (int j = 0; j < 4; ++j) {
        int c   = tid + j * 256;        // 0..1023
        int row = c >> 3;
        int col = c & 7;                // 16B chunk within 128B row payload
        cp16(sdst + row * TSTRIDE + col * 16,
             src + (size_t)(row0 + row) * D_ + k0 + col * 8);
    }
}

__device__ __forceinline__ void stage_all(uint32_t st, int bm, int bn, int k0)
{
    stage_tile(st + T_A, g_xh, bm, k0);
    stage_tile(st + T_B, g_wh, bn, k0);
    asm volatile("cp.async.commit_group;" ::: "memory");
}

__global__ __launch_bounds__(256, 2) void gemm_kernel(float* __restrict__ C)
{
    extern __shared__ char smem[];
    uint32_t sbase;
    asm("{ .reg .u64 t; cvta.to.shared.u64 t, %1; cvt.u32.u64 %0, t; }"
        : "=r"(sbase) : "l"(smem));

    const int tid  = threadIdx.x;
    const int wid  = tid >> 5;
    const int lane = tid & 31;
    const int wm   = wid & 1;          // 2 warps along M
    const int wn   = wid >> 1;         // 4 warps along N
    const int bm   = blockIdx.y * 128;
    const int bn   = blockIdx.x * 128;

    float acc[4][4][4];
    #pragma unroll
    for (int i = 0; i < 4; ++i)
        #pragma unroll
        for (int j = 0; j < 4; ++j)
            #pragma unroll
            for (int e = 0; e < 4; ++e) acc[i][j][e] = 0.f;

    const uint32_t lrow  = (uint32_t)(lane & 15);
    const uint32_t lkoff = (uint32_t)((lane >> 4) * 16);

    stage_all(sbase, bm, bn, 0);       // prologue: stage 0

    for (int it = 0; it < NITER; ++it) {
        const uint32_t st = sbase + (uint32_t)(it & 1) * STAGE_B;

        __syncthreads();               // all reads of the slot we refill are done
        if (it + 1 < NITER) {
            stage_all(sbase + (uint32_t)((it + 1) & 1) * STAGE_B, bm, bn, (it + 1) * KC);
            asm volatile("cp.async.wait_group 1;" ::: "memory");
        } else {
            asm volatile("cp.async.wait_group 0;" ::: "memory");
        }
        __syncthreads();               // current stage visible to all warps

        #pragma unroll
        for (int kk = 0; kk < 4; ++kk) {
            const uint32_t kb = (uint32_t)(kk * 32) + lkoff;

            // batched fragment loads: 6 LDSMs back-to-back, then 16 MMAs
            uint32_t a[4][4], bf[4][2];
            {
                uint32_t r0[4], r1[4];
                ldsm_x4(r0, st + T_B + ((uint32_t)(wn * 32 +  0) + lrow) * TSTRIDE + kb);
                ldsm_x4(r1, st + T_B + ((uint32_t)(wn * 32 + 16) + lrow) * TSTRIDE + kb);
                #pragma unroll
                for (int mt = 0; mt < 4; ++mt)
                    ldsm_x4(a[mt], st + T_A + ((uint32_t)(wm * 64 + mt * 16) + lrow) * TSTRIDE + kb);
                bf[0][0] = r0[0]; bf[0][1] = r0[2];
                bf[1][0] = r0[1]; bf[1][1] = r0[3];
                bf[2][0] = r1[0]; bf[2][1] = r1[2];
                bf[3][0] = r1[1]; bf[3][1] = r1[3];
            }

            #pragma unroll
            for (int mt = 0; mt < 4; ++mt)
                #pragma unroll
                for (int nt = 0; nt < 4; ++nt)
                    mma16816(acc[mt][nt], a[mt], bf[nt]);
        }
    }

    // Epilogue: direct float2 stores
    const int er = lane >> 2;
    const int ec = (lane & 3) * 2;
    #pragma unroll
    for (int mt = 0; mt < 4; ++mt) {
        const int row = bm + wm * 64 + mt * 16 + er;
        #pragma unroll
        for (int nt = 0; nt < 4; ++nt) {
            const int col = bn + wn * 32 + nt * 8 + ec;
            *(float2*)(C + (size_t)row * O_ + col) =
                make_float2(acc[mt][nt][0], acc[mt][nt][1]);
            *(float2*)(C + (size_t)(row + 8) * O_ + col) =
                make_float2(acc[mt][nt][2], acc[mt][nt][3]);
        }
    }
}

// ---------------------------------------------------------------------------
extern "C" void kernel_launch(void* const* d_in, const int* in_sizes, int n_in,
                              void* d_out, int out_size)
{
    const float*         x      = (const float*)d_in[0];
    const float*         w      = (const float*)d_in[1];
    const float*         wn     = (const float*)d_in[2];
    const int*           perm   = (const int*)d_in[3];
    const unsigned char* stored = (const unsigned char*)d_in[4];
    const int*           pb     = (const int*)d_in[5];
    float*               out    = (float*)d_out;

    (void)in_sizes; (void)n_in; (void)out_size;

    static bool attr_set = false;
    if (!attr_set) {
        cudaFuncSetAttribute(gemm_kernel, cudaFuncAttributeMaxDynamicSharedMemorySize,
                             SMEM_GEMM);
        attr_set = true;
    }

    mean_p1<<<dim3(32, 8), 128>>>(x, pb);
    mean_p2<<<16, 256>>>(pb);
    rank_kernel<<<32, 512>>>(perm);
    gate_kernel<<<1, 1024>>>(stored);
    split_kernel<<<XBLKS_ + WBLKS_, 256>>>(x, w, wn);   // 24576 blocks

    dim3 grid(O_ / 128, M_ / 128);   // (32, 64)
    gemm_kernel<<<grid, 256, SMEM_GEMM>>>(out);
}

// round 9
// speedup vs baseline: 3.2200x; 1.0174x over previous
#include <cuda_runtime.h>
#include <cuda_bf16.h>
#include <cuda_fp16.h>
#include <cstdint>

// Problem dims (fixed by the reference)
#define B_      4
#define S_      2048
#define D_      4096
#define O_      4096
#define M_      8192
#define TOPK_   2048
#define NMASKS_ 100

// ---------------------------------------------------------------------------
// Static device scratch (no runtime allocation allowed)
// ---------------------------------------------------------------------------
__device__ float g_psum[8][D_];
__device__ unsigned char g_amask[D_];
__device__ int g_counts[NMASKS_];
__device__ float g_mask[D_];
__device__ __align__(16) __half g_xh[(size_t)M_ * D_];   // fp16(x)
__device__ __align__(16) __half g_wh[(size_t)O_ * D_];   // fp16(weff)

// ---------------------------------------------------------------------------
// K1: partial column sums of x[0, 0..pb, :] over 8 row chunks
// grid (32, 8), 128 threads.  y==0 blocks also zero g_amask.
// ---------------------------------------------------------------------------
__global__ void mean_p1(const float* __restrict__ x, const int* __restrict__ pb)
{
    const int d = blockIdx.x * 128 + threadIdx.x;
    if (blockIdx.y == 0) g_amask[d] = 0;
    const int rows  = pb[0] + 1;
    const int chunk = (rows + 7) / 8;
    const int r0 = blockIdx.y * chunk;
    const int r1 = (r0 + chunk < rows) ? (r0 + chunk) : rows;
    float s = 0.f;
    int r = r0;
    for (; r + 4 <= r1; r += 4) {
        s += x[(size_t)(r + 0) * D_ + d];
        s += x[(size_t)(r + 1) * D_ + d];
        s += x[(size_t)(r + 2) * D_ + d];
        s += x[(size_t)(r + 3) * D_ + d];
    }
    for (; r < r1; ++r) s += x[(size_t)r * D_ + d];
    g_psum[blockIdx.y][d] = s;
}

// ---------------------------------------------------------------------------
// K2: reduce partials -> f, exact top-k rank by counting, scatter via perm.
// 32 blocks x 512 threads. Block b handles j in [b*128, (b+1)*128);
// 4 threads per j scan 1024 i each.
// rank(j) = #{i : key_i > key_j  or (key_i == key_j and i < j)}
// ---------------------------------------------------------------------------
__global__ void rank_kernel(const int* __restrict__ perm, const int* __restrict__ pb)
{
    __shared__ unsigned int keys[D_];
    __shared__ int sr[128][4];

    const int t = threadIdx.x;
    const float inv_note = 1.0f;   (void)inv_note;
    const int rows = pb[0] + 1;

    // identical summation order and division as a dedicated mean kernel
    for (int j = t; j < D_; j += 512) {
        float s = 0.f;
        #pragma unroll
        for (int y = 0; y < 8; ++y) s += g_psum[y][j];
        keys[j] = __float_as_uint(fabsf(s / (float)rows));
    }
    __syncthreads();

    const int jl = t & 127;
    const int h  = t >> 7;                       // 0..3
    const int j  = blockIdx.x * 128 + jl;
    const unsigned int kj = keys[j];
    int r = 0;
    const int i0 = h * 1024;
    #pragma unroll 8
    for (int i = i0; i < i0 + 1024; ++i) {
        const unsigned int ki = keys[i];
        r += (ki > kj) || (ki == kj && i < j);
    }
    sr[jl][h] = r;
    __syncthreads();

    if (t < 128) {
        const int rank = sr[t][0] + sr[t][1] + sr[t][2] + sr[t][3];
        if (rank < TOPK_)
            g_amask[perm[blockIdx.x * 128 + t]] = 1;   // perm: no conflicts
    }
}

// ---------------------------------------------------------------------------
// K3: overlap counts — one block per stored mask, dp4a byte dot product
// ---------------------------------------------------------------------------
__global__ void count_kernel(const unsigned char* __restrict__ stored)
{
    __shared__ int wsum[4];
    const int m = blockIdx.x;
    const int t = threadIdx.x;                 // 128 threads
    const uint32_t* am = (const uint32_t*)g_amask;
    const uint32_t* sm = (const uint32_t*)(stored + (size_t)m * D_);
    int c = 0;
    #pragma unroll
    for (int j = 0; j < 8; ++j) {
        const int i = t + j * 128;             // 1024 words
        const uint32_t v = am[i] & sm[i];
        asm("dp4a.s32.s32 %0, %1, %2, %0;" : "+r"(c) : "r"(v), "r"(0x01010101));
    }
    #pragma unroll
    for (int o = 16; o > 0; o >>= 1) c += __shfl_down_sync(0xffffffffu, c, o);
    if ((t & 31) == 0) wsum[t >> 5] = c;
    __syncthreads();
    if (t == 0) g_counts[m] = wsum[0] + wsum[1] + wsum[2] + wsum[3];
}

// ---------------------------------------------------------------------------
// K4: argmax (first max), gate, write g_mask. 1 block, 1024 threads.
// ---------------------------------------------------------------------------
__global__ void gatewrite_kernel(const unsigned char* __restrict__ stored)
{
    __shared__ int s_best[2];
    const int t = threadIdx.x;
    if (t == 0) {
        int best = -1, bi = 0;
        #pragma unroll 4
        for (int m = 0; m < NMASKS_; ++m) {
            const int c = g_counts[m];
            if (c > best) { best = c; bi = m; }   // first max (jnp.argmax)
        }
        s_best[0] = best; s_best[1] = bi;
    }
    __syncthreads();
    const int gate = (s_best[0] >= 1229) ? 1 : 0;   // count/2048 >= float32(0.6)
    const unsigned char* brow = stored + (size_t)s_best[1] * D_;
    for (int d = t; d < D_; d += 1024)
        g_mask[d] = (gate && brow[d]) ? 1.0f : 0.0f;
}

// ---------------------------------------------------------------------------
// K5 (merged): blocks [0, 16384)      -> x -> fp16
//              blocks [16384, 24576)  -> weff = w + mask*wn -> fp16
// ---------------------------------------------------------------------------
#define XBLKS_ ((int)(((size_t)M_ * D_ / 8) / 256))   // 16384
#define WBLKS_ ((int)(((size_t)O_ * D_ / 8) / 256))   // 8192

__global__ void split_kernel(const float* __restrict__ x,
                             const float* __restrict__ w,
                             const float* __restrict__ wn)
{
    if (blockIdx.x < XBLKS_) {
        size_t i = ((size_t)blockIdx.x * 256 + threadIdx.x) * 8;
        float4 v0 = *(const float4*)(x + i);
        float4 v1 = *(const float4*)(x + i + 4);
        float v[8] = {v0.x, v0.y, v0.z, v0.w, v1.x, v1.y, v1.z, v1.w};
        __align__(16) __half h[8];
        #pragma unroll
        for (int j = 0; j < 8; ++j) h[j] = __float2half(v[j]);
        *(uint4*)(g_xh + i) = *(uint4*)h;
    } else {
        size_t i = ((size_t)(blockIdx.x - XBLKS_) * 256 + threadIdx.x) * 8;
        const int dbase = (int)(i & (size_t)(D_ - 1));
        float4 w0 = *(const float4*)(w + i);
        float4 w1 = *(const float4*)(w + i + 4);
        float4 n0 = *(const float4*)(wn + i);
        float4 n1 = *(const float4*)(wn + i + 4);
        float wv[8] = {w0.x, w0.y, w0.z, w0.w, w1.x, w1.y, w1.z, w1.w};
        float nv[8] = {n0.x, n0.y, n0.z, n0.w, n1.x, n1.y, n1.z, n1.w};
        __align__(16) __half h[8];
        #pragma unroll
        for (int j = 0; j < 8; ++j)
            h[j] = __float2half(fmaf(g_mask[dbase + j], nv[j], wv[j]));
        *(uint4*)(g_wh + i) = *(uint4*)h;
    }
}

// ---------------------------------------------------------------------------
// K6: fp16 GEMM via mma.sync (HMMA), fp32 accumulate
//     C[M,N] = Xfp16[M,K] * Wfp16[N,K]^T
//     128x128 CTA tile, 8 warps of 64x32, KC=64, 3-stage cp.async pipeline,
//     ONE __syncthreads per iteration, 2 CTAs/SM.
// ---------------------------------------------------------------------------
#define KC        64
#define NITER     (D_ / KC)              // 64
#define TSTRIDE   144                    // 128B payload + 16B pad
#define TILE_B    (128 * TSTRIDE)        // 18432
#define T_A       0
#define T_B       TILE_B
#define STAGE_B   (2 * TILE_B)           // 36864
#define NSTAGE    3
#define SMEM_GEMM (NSTAGE * STAGE_B)     // 110592 (x2 CTAs = 221KB <= 228KB)

__device__ __forceinline__ void ldsm_x4(uint32_t* r, uint32_t addr)
{
    asm volatile("ldmatrix.sync.aligned.m8n8.x4.shared.b16 {%0,%1,%2,%3}, [%4];"
                 : "=r"(r[0]), "=r"(r[1]), "=r"(r[2]), "=r"(r[3]) : "r"(addr));
}

__device__ __forceinline__ void mma16816(float* d, const uint32_t* a, const uint32_t* b)
{
    asm volatile("mma.sync.aligned.m16n8k16.row.col.f32.f16.f16.f32 "
                 "{%0,%1,%2,%3}, {%4,%5,%6,%7}, {%8,%9}, {%0,%1,%2,%3};"
                 : "+f"(d[0]), "+f"(d[1]), "+f"(d[2]), "+f"(d[3])
                 : "r"(a[0]), "r"(a[1]), "r"(a[2]), "r"(a[3]), "r"(b[0]), "r"(b[1]));
}

__device__ __forceinline__ void cp16(uint32_t dst, const void* src)
{
    asm volatile("cp.async.cg.shared.global [%0], [%1], 16;" :: "r"(dst), "l"(src));
}

__device__ __forceinline__ void stage_tile(uint32_t sdst, const __half* __restrict__ src,
                                           int row0, int k0)
{
    const int tid = threadIdx.x;
    #pragma unroll
    for (int j = 0; j < 4; ++j) {
        int c   = tid + j * 256;        // 0..1023
        int row = c >> 3;
        int col = c & 7;                // 16B chunk within 128B row payload
        cp16(sdst + row * TSTRIDE + col * 16,
             src + (size_t)(row0 + row) * D_ + k0 + col * 8);
    }
}

__device__ __forceinline__ void stage_all(uint32_t st, int bm, int bn, int k0)
{
    stage_tile(st + T_A, g_xh, bm, k0);
    stage_tile(st + T_B, g_wh, bn, k0);
    asm volatile("cp.async.commit_group;" ::: "memory");
}

__global__ __launch_bounds__(256, 2) void gemm_kernel(float* __restrict__ C)
{
    extern __shared__ char smem[];
    uint32_t sbase;
    asm("{ .reg .u64 t; cvta.to.shared.u64 t, %1; cvt.u32.u64 %0, t; }"
        : "=r"(sbase) : "l"(smem));

    const int tid  = threadIdx.x;
    const int wid  = tid >> 5;
    const int lane = tid & 31;
    const int wm   = wid & 1;          // 2 warps along M
    const int wn   = wid >> 1;         // 4 warps along N
    const int bm   = blockIdx.y * 128;
    const int bn   = blockIdx.x * 128;

    float acc[4][4][4];
    #pragma unroll
    for (int i = 0; i < 4; ++i)
        #pragma unroll
        for (int j = 0; j < 4; ++j)
            #pragma unroll
            for (int e = 0; e < 4; ++e) acc[i][j][e] = 0.f;

    const uint32_t lrow  = (uint32_t)(lane & 15);
    const uint32_t lkoff = (uint32_t)((lane >> 4) * 16);

    // prologue: stages 0, 1
    stage_all(sbase + 0 * STAGE_B, bm, bn, 0 * KC);
    stage_all(sbase + 1 * STAGE_B, bm, bn, 1 * KC);

    uint32_t cur = sbase;                    // slot it % 3
    uint32_t fut = sbase + 2 * STAGE_B;      // slot (it+2) % 3

    for (int it = 0; it < NITER; ++it) {
        // own group `it` done (pending {it, it+1} -> leave 1)
        asm volatile("cp.async.wait_group 1;" ::: "memory");
        // barrier: (a) every warp's group-it wait done -> whole slot `cur`
        // visible; (b) all warps finished reading slot (it-1)%3 == fut,
        // so it is safe to overwrite it below.
        __syncthreads();

        if (it + 2 < NITER) {
            stage_all(fut, bm, bn, (it + 2) * KC);
        } else {
            asm volatile("cp.async.commit_group;" ::: "memory");  // keep counts
        }

        #pragma unroll
        for (int kk = 0; kk < 4; ++kk) {
            const uint32_t kb = (uint32_t)(kk * 32) + lkoff;

            uint32_t a[4][4], bf[4][2];
            {
                uint32_t r0[4], r1[4];
                ldsm_x4(r0, cur + T_B + ((uint32_t)(wn * 32 +  0) + lrow) * TSTRIDE + kb);
                ldsm_x4(r1, cur + T_B + ((uint32_t)(wn * 32 + 16) + lrow) * TSTRIDE + kb);
                #pragma unroll
                for (int mt = 0; mt < 4; ++mt)
                    ldsm_x4(a[mt], cur + T_A + ((uint32_t)(wm * 64 + mt * 16) + lrow) * TSTRIDE + kb);
                bf[0][0] = r0[0]; bf[0][1] = r0[2];
                bf[1][0] = r0[1]; bf[1][1] = r0[3];
                bf[2][0] = r1[0]; bf[2][1] = r1[2];
                bf[3][0] = r1[1]; bf[3][1] = r1[3];
            }

            #pragma unroll
            for (int mt = 0; mt < 4; ++mt)
                #pragma unroll
                for (int nt = 0; nt < 4; ++nt)
                    mma16816(acc[mt][nt], a[mt], bf[nt]);
        }

        // rotate slots: cur <- cur+1, fut <- fut+1 (mod 3)
        const uint32_t top = sbase + 2 * STAGE_B;
        cur = (cur == top) ? sbase : cur + STAGE_B;
        fut = (fut == top) ? sbase : fut + STAGE_B;
    }

    // Epilogue: direct float2 stores
    const int er = lane >> 2;
    const int ec = (lane & 3) * 2;
    #pragma unroll
    for (int mt = 0; mt < 4; ++mt) {
        const int row = bm + wm * 64 + mt * 16 + er;
        #pragma unroll
        for (int nt = 0; nt < 4; ++nt) {
            const int col = bn + wn * 32 + nt * 8 + ec;
            *(float2*)(C + (size_t)row * O_ + col) =
                make_float2(acc[mt][nt][0], acc[mt][nt][1]);
            *(float2*)(C + (size_t)(row + 8) * O_ + col) =
                make_float2(acc[mt][nt][2], acc[mt][nt][3]);
        }
    }
}

// ---------------------------------------------------------------------------
extern "C" void kernel_launch(void* const* d_in, const int* in_sizes, int n_in,
                              void* d_out, int out_size)
{
    const float*         x      = (const float*)d_in[0];
    const float*         w      = (const float*)d_in[1];
    const float*         wn     = (const float*)d_in[2];
    const int*           perm   = (const int*)d_in[3];
    const unsigned char* stored = (const unsigned char*)d_in[4];
    const int*           pb     = (const int*)d_in[5];
    float*               out    = (float*)d_out;

    (void)in_sizes; (void)n_in; (void)out_size;

    static bool attr_set = false;
    if (!attr_set) {
        cudaFuncSetAttribute(gemm_kernel, cudaFuncAttributeMaxDynamicSharedMemorySize,
                             SMEM_GEMM);
        attr_set = true;
    }

    mean_p1<<<dim3(32, 8), 128>>>(x, pb);          // 0
    rank_kernel<<<32, 512>>>(perm, pb);            // 1
    count_kernel<<<NMASKS_, 128>>>(stored);        // 2
    gatewrite_kernel<<<1, 1024>>>(stored);         // 3
    split_kernel<<<XBLKS_ + WBLKS_, 256>>>(x, w, wn);  // 4
    dim3 grid(O_ / 128, M_ / 128);                 // 5 <- ncu capture slot
    gemm_kernel<<<grid, 256, SMEM_GEMM>>>(out);
}

// round 10
// speedup vs baseline: 3.2457x; 1.0080x over previous
#include <cuda_runtime.h>
#include <cuda_bf16.h>
#include <cuda_fp16.h>
#include <cstdint>

// Problem dims (fixed by the reference)
#define B_      4
#define S_      2048
#define D_      4096
#define O_      4096
#define M_      8192
#define TOPK_   2048
#define NMASKS_ 100

// ---------------------------------------------------------------------------
// Static device scratch (no runtime allocation allowed)
// ---------------------------------------------------------------------------
__device__ float g_psum[8][D_];
__device__ unsigned char g_amask[D_];
__device__ int g_best;                                   // (count<<7) | (127-m)
__device__ __align__(16) __half g_xh[(size_t)M_ * D_];   // fp16(x)
__device__ __align__(16) __half g_wh[(size_t)O_ * D_];   // fp16(weff)

// ---------------------------------------------------------------------------
// K1: partial column sums of x[0, 0..pb, :] over 8 row chunks
// grid (32, 8), 128 threads.  y==0 blocks also zero g_amask; resets g_best.
// ---------------------------------------------------------------------------
__global__ void mean_p1(const float* __restrict__ x, const int* __restrict__ pb)
{
    const int d = blockIdx.x * 128 + threadIdx.x;
    if (blockIdx.y == 0) {
        g_amask[d] = 0;
        if (blockIdx.x == 0 && threadIdx.x == 0) g_best = 0;
    }
    const int rows  = pb[0] + 1;
    const int chunk = (rows + 7) / 8;
    const int r0 = blockIdx.y * chunk;
    const int r1 = (r0 + chunk < rows) ? (r0 + chunk) : rows;
    float s = 0.f;
    int r = r0;
    for (; r + 4 <= r1; r += 4) {
        s += x[(size_t)(r + 0) * D_ + d];
        s += x[(size_t)(r + 1) * D_ + d];
        s += x[(size_t)(r + 2) * D_ + d];
        s += x[(size_t)(r + 3) * D_ + d];
    }
    for (; r < r1; ++r) s += x[(size_t)r * D_ + d];
    g_psum[blockIdx.y][d] = s;
}

// ---------------------------------------------------------------------------
// K2: reduce partials -> f, exact top-k rank by counting, scatter via perm.
// 32 blocks x 512 threads. rank(j) = #{i : k_i > k_j or (k_i==k_j and i<j)}
// ---------------------------------------------------------------------------
__global__ void rank_kernel(const int* __restrict__ perm, const int* __restrict__ pb)
{
    __shared__ unsigned int keys[D_];
    __shared__ int sr[128][4];

    const int t = threadIdx.x;
    const int rows = pb[0] + 1;

    for (int j = t; j < D_; j += 512) {
        float s = 0.f;
        #pragma unroll
        for (int y = 0; y < 8; ++y) s += g_psum[y][j];
        keys[j] = __float_as_uint(fabsf(s / (float)rows));
    }
    __syncthreads();

    const int jl = t & 127;
    const int h  = t >> 7;                       // 0..3
    const int j  = blockIdx.x * 128 + jl;
    const unsigned int kj = keys[j];
    int r = 0;
    const int i0 = h * 1024;
    #pragma unroll 8
    for (int i = i0; i < i0 + 1024; ++i) {
        const unsigned int ki = keys[i];
        r += (ki > kj) || (ki == kj && i < j);
    }
    sr[jl][h] = r;
    __syncthreads();

    if (t < 128) {
        const int rank = sr[t][0] + sr[t][1] + sr[t][2] + sr[t][3];
        if (rank < TOPK_)
            g_amask[perm[blockIdx.x * 128 + t]] = 1;   // perm: no conflicts
    }
}

// ---------------------------------------------------------------------------
// K3: overlap counts + argmax via atomicMax of (count<<7)|(127-m).
// Ties in count -> larger (127-m) -> smaller m = first max (jnp.argmax).
// ---------------------------------------------------------------------------
__global__ void count_kernel(const unsigned char* __restrict__ stored)
{
    __shared__ int wsum[4];
    const int m = blockIdx.x;
    const int t = threadIdx.x;                 // 128 threads
    const uint32_t* am = (const uint32_t*)g_amask;
    const uint32_t* sm = (const uint32_t*)(stored + (size_t)m * D_);
    int c = 0;
    #pragma unroll
    for (int j = 0; j < 8; ++j) {
        const int i = t + j * 128;             // 1024 words
        const uint32_t v = am[i] & sm[i];
        asm("dp4a.s32.s32 %0, %1, %2, %0;" : "+r"(c) : "r"(v), "r"(0x01010101));
    }
    #pragma unroll
    for (int o = 16; o > 0; o >>= 1) c += __shfl_down_sync(0xffffffffu, c, o);
    if ((t & 31) == 0) wsum[t >> 5] = c;
    __syncthreads();
    if (t == 0) {
        const int total = wsum[0] + wsum[1] + wsum[2] + wsum[3];
        atomicMax(&g_best, (total << 7) | (127 - m));
    }
}

// ---------------------------------------------------------------------------
// K4 (merged): blocks [0, 16384)      -> x -> fp16
//              blocks [16384, 24576)  -> weff = w + gate*mask*wn -> fp16
// gate/mask decoded from g_best + stored (row is L2-hot, broadcast).
// ---------------------------------------------------------------------------
#define XBLKS_ ((int)(((size_t)M_ * D_ / 8) / 256))   // 16384
#define WBLKS_ ((int)(((size_t)O_ * D_ / 8) / 256))   // 8192

__global__ void split_kernel(const float* __restrict__ x,
                             const float* __restrict__ w,
                             const float* __restrict__ wn,
                             const unsigned char* __restrict__ stored)
{
    if (blockIdx.x < XBLKS_) {
        size_t i = ((size_t)blockIdx.x * 256 + threadIdx.x) * 8;
        float4 v0 = *(const float4*)(x + i);
        float4 v1 = *(const float4*)(x + i + 4);
        float v[8] = {v0.x, v0.y, v0.z, v0.w, v1.x, v1.y, v1.z, v1.w};
        __align__(16) __half h[8];
        #pragma unroll
        for (int j = 0; j < 8; ++j) h[j] = __float2half(v[j]);
        *(uint4*)(g_xh + i) = *(uint4*)h;
    } else {
        size_t i = ((size_t)(blockIdx.x - XBLKS_) * 256 + threadIdx.x) * 8;
        const int dbase = (int)(i & (size_t)(D_ - 1));
        const int best  = g_best;
        const int gate  = ((best >> 7) >= 1229);   // count/2048 >= float32(0.6)
        const unsigned char* brow = stored + (size_t)(127 - (best & 127)) * D_;
        uint2 bb = *(const uint2*)(brow + dbase);
        const unsigned char* bp = (const unsigned char*)&bb;
        float4 w0 = *(const float4*)(w + i);
        float4 w1 = *(const float4*)(w + i + 4);
        float4 n0 = *(const float4*)(wn + i);
        float4 n1 = *(const float4*)(wn + i + 4);
        float wv[8] = {w0.x, w0.y, w0.z, w0.w, w1.x, w1.y, w1.z, w1.w};
        float nv[8] = {n0.x, n0.y, n0.z, n0.w, n1.x, n1.y, n1.z, n1.w};
        __align__(16) __half h[8];
        #pragma unroll
        for (int j = 0; j < 8; ++j) {
            const float mj = (gate && bp[j]) ? 1.0f : 0.0f;
            h[j] = __float2half(fmaf(mj, nv[j], wv[j]));
        }
        *(uint4*)(g_wh + i) = *(uint4*)h;
    }
}

// ---------------------------------------------------------------------------
// K5: fp16 GEMM via mma.sync (HMMA), fp32 accumulate
//     128x128 CTA tile, 8 warps of 64x32, KC=64, 3-stage cp.async pipeline,
//     2 CTAs/SM, warp phase-staggered kk order to overlap LDSM and MMA.
// ---------------------------------------------------------------------------
#define KC        64
#define NITER     (D_ / KC)              // 64
#define TSTRIDE   144                    // 128B payload + 16B pad
#define TILE_B    (128 * TSTRIDE)        // 18432
#define T_A       0
#define T_B       TILE_B
#define STAGE_B   (2 * TILE_B)           // 36864
#define NSTAGE    3
#define SMEM_GEMM (NSTAGE * STAGE_B)     // 110592 (x2 CTAs = 221KB <= 228KB)

__device__ __forceinline__ void ldsm_x4(uint32_t* r, uint32_t addr)
{
    asm volatile("ldmatrix.sync.aligned.m8n8.x4.shared.b16 {%0,%1,%2,%3}, [%4];"
                 : "=r"(r[0]), "=r"(r[1]), "=r"(r[2]), "=r"(r[3]) : "r"(addr));
}

__device__ __forceinline__ void mma16816(float* d, const uint32_t* a, const uint32_t* b)
{
    asm volatile("mma.sync.aligned.m16n8k16.row.col.f32.f16.f16.f32 "
                 "{%0,%1,%2,%3}, {%4,%5,%6,%7}, {%8,%9}, {%0,%1,%2,%3};"
                 : "+f"(d[0]), "+f"(d[1]), "+f"(d[2]), "+f"(d[3])
                 : "r"(a[0]), "r"(a[1]), "r"(a[2]), "r"(a[3]), "r"(b[0]), "r"(b[1]));
}

__device__ __forceinline__ void cp16(uint32_t dst, const void* src)
{
    asm volatile("cp.async.cg.shared.global [%0], [%1], 16;" :: "r"(dst), "l"(src));
}

__device__ __forceinline__ void stage_tile(uint32_t sdst, const __half* __restrict__ src,
                                           int row0, int k0)
{
    const int tid = threadIdx.x;
    #pragma unroll
    for (int j = 0; j < 4; ++j) {
        int c   = tid + j * 256;        // 0..1023
        int row = c >> 3;
        int col = c & 7;                // 16B chunk within 128B row payload
        cp16(sdst + row * TSTRIDE + col * 16,
             src + (size_t)(row0 + row) * D_ + k0 + col * 8);
    }
}

__device__ __forceinline__ void stage_all(uint32_t st, int bm, int bn, int k0)
{
    stage_tile(st + T_A, g_xh, bm, k0);
    stage_tile(st + T_B, g_wh, bn, k0);
    asm volatile("cp.async.commit_group;" ::: "memory");
}

__global__ __launch_bounds__(256, 2) void gemm_kernel(float* __restrict__ C)
{
    extern __shared__ char smem[];
    uint32_t sbase;
    asm("{ .reg .u64 t; cvta.to.shared.u64 t, %1; cvt.u32.u64 %0, t; }"
        : "=r"(sbase) : "l"(smem));

    const int tid  = threadIdx.x;
    const int wid  = tid >> 5;
    const int lane = tid & 31;
    const int wm   = wid & 1;          // 2 warps along M
    const int wn   = wid >> 1;         // 4 warps along N
    const int bm   = blockIdx.y * 128;
    const int bn   = blockIdx.x * 128;
    const int kk0  = (wid & 4) ? 2 : 0;   // phase stagger: half the warps offset

    float acc[4][4][4];
    #pragma unroll
    for (int i = 0; i < 4; ++i)
        #pragma unroll
        for (int j = 0; j < 4; ++j)
            #pragma unroll
            for (int e = 0; e < 4; ++e) acc[i][j][e] = 0.f;

    const uint32_t lrow  = (uint32_t)(lane & 15);
    const uint32_t lkoff = (uint32_t)((lane >> 4) * 16);

    // prologue: stages 0, 1
    stage_all(sbase + 0 * STAGE_B, bm, bn, 0 * KC);
    stage_all(sbase + 1 * STAGE_B, bm, bn, 1 * KC);

    uint32_t cur = sbase;                    // slot it % 3
    uint32_t fut = sbase + 2 * STAGE_B;      // slot (it+2) % 3

    for (int it = 0; it < NITER; ++it) {
        asm volatile("cp.async.wait_group 1;" ::: "memory");
        // (a) group-it waits done everywhere -> slot `cur` fully visible;
        // (b) slot `fut` == (it-1)%3 was last read before this barrier ->
        //     safe to overwrite below.
        __syncthreads();

        if (it + 2 < NITER) {
            stage_all(fut, bm, bn, (it + 2) * KC);
        } else {
            asm volatile("cp.async.commit_group;" ::: "memory");  // keep counts
        }

        #pragma unroll
        for (int i2 = 0; i2 < 4; ++i2) {
            const int kk = (i2 + kk0) & 3;         // staggered phase per warp-half
            const uint32_t kb = (uint32_t)(kk * 32) + lkoff;

            uint32_t a[4][4], bf[4][2];
            {
                uint32_t r0[4], r1[4];
                // order: r0 first, A rows, r1 last -> first MMAs wait on 2 LDSMs
                ldsm_x4(r0, cur + T_B + ((uint32_t)(wn * 32 +  0) + lrow) * TSTRIDE + kb);
                #pragma unroll
                for (int mt = 0; mt < 4; ++mt)
                    ldsm_x4(a[mt], cur + T_A + ((uint32_t)(wm * 64 + mt * 16) + lrow) * TSTRIDE + kb);
                ldsm_x4(r1, cur + T_B + ((uint32_t)(wn * 32 + 16) + lrow) * TSTRIDE + kb);
                bf[0][0] = r0[0]; bf[0][1] = r0[2];
                bf[1][0] = r0[1]; bf[1][1] = r0[3];
                bf[2][0] = r1[0]; bf[2][1] = r1[2];
                bf[3][0] = r1[1]; bf[3][1] = r1[3];
            }

            // r0-dependent MMAs first, then r1-dependent
            #pragma unroll
            for (int mt = 0; mt < 4; ++mt) {
                mma16816(acc[mt][0], a[mt], bf[0]);
                mma16816(acc[mt][1], a[mt], bf[1]);
            }
            #pragma unroll
            for (int mt = 0; mt < 4; ++mt) {
                mma16816(acc[mt][2], a[mt], bf[2]);
                mma16816(acc[mt][3], a[mt], bf[3]);
            }
        }

        const uint32_t top = sbase + 2 * STAGE_B;
        cur = (cur == top) ? sbase : cur + STAGE_B;
        fut = (fut == top) ? sbase : fut + STAGE_B;
    }

    // Epilogue: direct float2 stores
    const int er = lane >> 2;
    const int ec = (lane & 3) * 2;
    #pragma unroll
    for (int mt = 0; mt < 4; ++mt) {
        const int row = bm + wm * 64 + mt * 16 + er;
        #pragma unroll
        for (int nt = 0; nt < 4; ++nt) {
            const int col = bn + wn * 32 + nt * 8 + ec;
            *(float2*)(C + (size_t)row * O_ + col) =
                make_float2(acc[mt][nt][0], acc[mt][nt][1]);
            *(float2*)(C + (size_t)(row + 8) * O_ + col) =
                make_float2(acc[mt][nt][2], acc[mt][nt][3]);
        }
    }
}

// ---------------------------------------------------------------------------
extern "C" void kernel_launch(void* const* d_in, const int* in_sizes, int n_in,
                              void* d_out, int out_size)
{
    const float*         x      = (const float*)d_in[0];
    const float*         w      = (const float*)d_in[1];
    const float*         wn     = (const float*)d_in[2];
    const int*           perm   = (const int*)d_in[3];
    const unsigned char* stored = (const unsigned char*)d_in[4];
    const int*           pb     = (const int*)d_in[5];
    float*               out    = (float*)d_out;

    (void)in_sizes; (void)n_in; (void)out_size;

    static bool attr_set = false;
    if (!attr_set) {
        cudaFuncSetAttribute(gemm_kernel, cudaFuncAttributeMaxDynamicSharedMemorySize,
                             SMEM_GEMM);
        attr_set = true;
    }

    mean_p1<<<dim3(32, 8), 128>>>(x, pb);                      // 0
    rank_kernel<<<32, 512>>>(perm, pb);                        // 1
    count_kernel<<<NMASKS_, 128>>>(stored);                    // 2
    split_kernel<<<XBLKS_ + WBLKS_, 256>>>(x, w, wn, stored);  // 3
    dim3 grid(O_ / 128, M_ / 128);
    gemm_kernel<<<grid, 256, SMEM_GEMM>>>(out);                // 4
}

// round 11
// speedup vs baseline: 3.3990x; 1.0472x over previous
#include <cuda_runtime.h>
#include <cuda_bf16.h>
#include <cuda_fp16.h>
#include <cstdint>

// Problem dims (fixed by the reference)
#define B_      4
#define S_      2048
#define D_      4096
#define O_      4096
#define M_      8192
#define TOPK_   2048
#define NMASKS_ 100

// ---------------------------------------------------------------------------
// Static device scratch (no runtime allocation allowed)
// ---------------------------------------------------------------------------
__device__ float g_psum[8][D_];
__device__ unsigned char g_amask[D_];
__device__ int g_counts[NMASKS_];
__device__ __align__(16) __half g_xh[(size_t)M_ * D_];   // fp16(x)
__device__ __align__(16) __half g_wh[(size_t)O_ * D_];   // fp16(weff)

// ---------------------------------------------------------------------------
// K1: partial column sums of x[0, 0..pb, :] over 8 row chunks
// grid (32, 8), 128 threads. y==0 zeroes g_amask; (0,0) zeroes g_counts.
// ---------------------------------------------------------------------------
__global__ void mean_p1(const float* __restrict__ x, const int* __restrict__ pb)
{
    const int d = blockIdx.x * 128 + threadIdx.x;
    if (blockIdx.y == 0) {
        g_amask[d] = 0;
        if (blockIdx.x == 0 && threadIdx.x < NMASKS_) g_counts[threadIdx.x] = 0;
    }
    const int rows  = pb[0] + 1;
    const int chunk = (rows + 7) / 8;
    const int r0 = blockIdx.y * chunk;
    const int r1 = (r0 + chunk < rows) ? (r0 + chunk) : rows;
    float s = 0.f;
    int r = r0;
    for (; r + 4 <= r1; r += 4) {
        s += x[(size_t)(r + 0) * D_ + d];
        s += x[(size_t)(r + 1) * D_ + d];
        s += x[(size_t)(r + 2) * D_ + d];
        s += x[(size_t)(r + 3) * D_ + d];
    }
    for (; r < r1; ++r) s += x[(size_t)r * D_ + d];
    g_psum[blockIdx.y][d] = s;
}

// ---------------------------------------------------------------------------
// K2: reduce partials -> f, exact top-k rank, scatter via perm, AND
//     accumulate per-block partial overlap counts into g_counts.
// 32 blocks x 512 threads.
// rank(j) = #{i : k_i > k_j or (k_i == k_j and i < j)}
// ---------------------------------------------------------------------------
__global__ void rank_kernel(const int* __restrict__ perm, const int* __restrict__ pb,
                            const unsigned char* __restrict__ stored)
{
    __shared__ unsigned int keys[D_];
    __shared__ int sr[128][4];
    __shared__ int spos[128];
    __shared__ int ssel[128];

    const int t = threadIdx.x;
    const int rows = pb[0] + 1;

    for (int j = t; j < D_; j += 512) {
        float s = 0.f;
        #pragma unroll
        for (int y = 0; y < 8; ++y) s += g_psum[y][j];
        keys[j] = __float_as_uint(fabsf(s / (float)rows));
    }
    __syncthreads();

    const int jl = t & 127;
    const int h  = t >> 7;                       // 0..3
    const int j  = blockIdx.x * 128 + jl;
    const unsigned int kj = keys[j];
    int r = 0;
    const int i0 = h * 1024;
    #pragma unroll 8
    for (int i = i0; i < i0 + 1024; ++i) {
        const unsigned int ki = keys[i];
        r += (ki > kj) || (ki == kj && i < j);
    }
    sr[jl][h] = r;
    __syncthreads();

    if (t < 128) {
        const int rank = sr[t][0] + sr[t][1] + sr[t][2] + sr[t][3];
        const int pos  = perm[blockIdx.x * 128 + t];
        const int sel  = (rank < TOPK_) ? 1 : 0;
        spos[t] = pos;
        ssel[t] = sel;
        if (sel) g_amask[pos] = 1;               // perm: no conflicts
    }
    __syncthreads();

    // partial overlap counts: warp w handles masks m = w, w+16, ...
    const int warp = t >> 5, lane = t & 31;
    for (int m = warp; m < NMASKS_; m += 16) {
        const unsigned char* row = stored + (size_t)m * D_;
        int c = 0;
        #pragma unroll
        for (int i = lane; i < 128; i += 32)
            c += ssel[i] ? (int)row[spos[i]] : 0;
        #pragma unroll
        for (int o = 16; o > 0; o >>= 1) c += __shfl_down_sync(0xffffffffu, c, o);
        if (lane == 0) atomicAdd(&g_counts[m], c);
    }
}

// ---------------------------------------------------------------------------
// K3 (merged): blocks [0, 16384)      -> x -> fp16
//              blocks [16384, 24576)  -> weff = w + gate*mask*wn -> fp16
// W-half computes argmax/gate from g_counts (block-reduce, first-max ties).
// ---------------------------------------------------------------------------
#define XBLKS_ ((int)(((size_t)M_ * D_ / 8) / 256))   // 16384
#define WBLKS_ ((int)(((size_t)O_ * D_ / 8) / 256))   // 8192

__global__ void split_kernel(const float* __restrict__ x,
                             const float* __restrict__ w,
                             const float* __restrict__ wn,
                             const unsigned char* __restrict__ stored)
{
    if (blockIdx.x < XBLKS_) {
        size_t i = ((size_t)blockIdx.x * 256 + threadIdx.x) * 8;
        float4 v0 = *(const float4*)(x + i);
        float4 v1 = *(const float4*)(x + i + 4);
        float v[8] = {v0.x, v0.y, v0.z, v0.w, v1.x, v1.y, v1.z, v1.w};
        __align__(16) __half h[8];
        #pragma unroll
        for (int j = 0; j < 8; ++j) h[j] = __float2half(v[j]);
        *(uint4*)(g_xh + i) = *(uint4*)h;
    } else {
        __shared__ int smax[8];
        __shared__ int s_best;
        const int t = threadIdx.x;
        // block argmax of (count<<7)|(127-m): ties -> smaller m (first max)
        int v = 0;
        if (t < NMASKS_) v = (g_counts[t] << 7) | (127 - t);
        #pragma unroll
        for (int o = 16; o > 0; o >>= 1) v = max(v, __shfl_down_sync(0xffffffffu, v, o));
        if ((t & 31) == 0) smax[t >> 5] = v;
        __syncthreads();
        if (t == 0) {
            int b = smax[0];
            #pragma unroll
            for (int q = 1; q < 8; ++q) b = max(b, smax[q]);
            s_best = b;
        }
        __syncthreads();
        const int best = s_best;
        const int gate = ((best >> 7) >= 1229);   // count/2048 >= float32(0.6)
        const unsigned char* brow = stored + (size_t)(127 - (best & 127)) * D_;

        size_t i = ((size_t)(blockIdx.x - XBLKS_) * 256 + t) * 8;
        const int dbase = (int)(i & (size_t)(D_ - 1));
        uint2 bb = *(const uint2*)(brow + dbase);
        const unsigned char* bp = (const unsigned char*)&bb;
        float4 w0 = *(const float4*)(w + i);
        float4 w1 = *(const float4*)(w + i + 4);
        float4 n0 = *(const float4*)(wn + i);
        float4 n1 = *(const float4*)(wn + i + 4);
        float wv[8] = {w0.x, w0.y, w0.z, w0.w, w1.x, w1.y, w1.z, w1.w};
        float nv[8] = {n0.x, n0.y, n0.z, n0.w, n1.x, n1.y, n1.z, n1.w};
        __align__(16) __half h[8];
        #pragma unroll
        for (int j = 0; j < 8; ++j) {
            const float mj = (gate && bp[j]) ? 1.0f : 0.0f;
            h[j] = __float2half(fmaf(mj, nv[j], wv[j]));
        }
        *(uint4*)(g_wh + i) = *(uint4*)h;
    }
}

// ---------------------------------------------------------------------------
// K4: fp16 GEMM via mma.sync (HMMA), fp32 accumulate
//     128x128 CTA tile, 8 warps of 64x32, KC=64, 3-stage cp.async pipeline,
//     2 CTAs/SM, double-buffered fragments (LDSM kk+1 under MMA kk).
// ---------------------------------------------------------------------------
#define KC        64
#define NITER     (D_ / KC)              // 64
#define TSTRIDE   144                    // 128B payload + 16B pad
#define TILE_B    (128 * TSTRIDE)        // 18432
#define T_A       0
#define T_B       TILE_B
#define STAGE_B   (2 * TILE_B)           // 36864
#define NSTAGE    3
#define SMEM_GEMM (NSTAGE * STAGE_B)     // 110592 (x2 CTAs = 221KB <= 228KB)

__device__ __forceinline__ void ldsm_x4(uint32_t* r, uint32_t addr)
{
    asm volatile("ldmatrix.sync.aligned.m8n8.x4.shared.b16 {%0,%1,%2,%3}, [%4];"
                 : "=r"(r[0]), "=r"(r[1]), "=r"(r[2]), "=r"(r[3]) : "r"(addr));
}

__device__ __forceinline__ void mma16816(float* d, const uint32_t* a, const uint32_t* b)
{
    asm volatile("mma.sync.aligned.m16n8k16.row.col.f32.f16.f16.f32 "
                 "{%0,%1,%2,%3}, {%4,%5,%6,%7}, {%8,%9}, {%0,%1,%2,%3};"
                 : "+f"(d[0]), "+f"(d[1]), "+f"(d[2]), "+f"(d[3])
                 : "r"(a[0]), "r"(a[1]), "r"(a[2]), "r"(a[3]), "r"(b[0]), "r"(b[1]));
}

__device__ __forceinline__ void cp16(uint32_t dst, const void* src)
{
    asm volatile("cp.async.cg.shared.global [%0], [%1], 16;" :: "r"(dst), "l"(src));
}

__device__ __forceinline__ void stage_tile(uint32_t sdst, const __half* __restrict__ src,
                                           int row0, int k0)
{
    const int tid = threadIdx.x;
    #pragma unroll
    for (int j = 0; j < 4; ++j) {
        int c   = tid + j * 256;        // 0..1023
        int row = c >> 3;
        int col = c & 7;                // 16B chunk within 128B row payload
        cp16(sdst + row * TSTRIDE + col * 16,
             src + (size_t)(row0 + row) * D_ + k0 + col * 8);
    }
}

__device__ __forceinline__ void stage_all(uint32_t st, int bm, int bn, int k0)
{
    stage_tile(st + T_A, g_xh, bm, k0);
    stage_tile(st + T_B, g_wh, bn, k0);
    asm volatile("cp.async.commit_group;" ::: "memory");
}

__global__ __launch_bounds__(256, 2) void gemm_kernel(float* __restrict__ C)
{
    extern __shared__ char smem[];
    uint32_t sbase;
    asm("{ .reg .u64 t; cvta.to.shared.u64 t, %1; cvt.u32.u64 %0, t; }"
        : "=r"(sbase) : "l"(smem));

    const int tid  = threadIdx.x;
    const int wid  = tid >> 5;
    const int lane = tid & 31;
    const int wm   = wid & 1;          // 2 warps along M
    const int wn   = wid >> 1;         // 4 warps along N
    const int bm   = blockIdx.y * 128;
    const int bn   = blockIdx.x * 128;

    float acc[4][4][4];
    #pragma unroll
    for (int i = 0; i < 4; ++i)
        #pragma unroll
        for (int j = 0; j < 4; ++j)
            #pragma unroll
            for (int e = 0; e < 4; ++e) acc[i][j][e] = 0.f;

    const uint32_t lrow  = (uint32_t)(lane & 15);
    const uint32_t lkoff = (uint32_t)((lane >> 4) * 16);

    // per-warp fragment base offsets within a stage
    const uint32_t aoff = T_A + ((uint32_t)(wm * 64) + lrow) * TSTRIDE + lkoff;
    const uint32_t boff = T_B + ((uint32_t)(wn * 32) + lrow) * TSTRIDE + lkoff;

    // prologue: stages 0, 1
    stage_all(sbase + 0 * STAGE_B, bm, bn, 0 * KC);
    stage_all(sbase + 1 * STAGE_B, bm, bn, 1 * KC);

    uint32_t cur = sbase;                    // slot it % 3
    uint32_t fut = sbase + 2 * STAGE_B;      // slot (it+2) % 3

    for (int it = 0; it < NITER; ++it) {
        asm volatile("cp.async.wait_group 1;" ::: "memory");
        __syncthreads();   // slot `cur` visible everywhere; slot `fut` free

        uint32_t a[2][4][4], bf[2][4][2];

        // prologue loads for kk = 0 (buffer 0)
        {
            uint32_t r0[4], r1[4];
            ldsm_x4(r0, cur + boff);
            #pragma unroll
            for (int mt = 0; mt < 4; ++mt)
                ldsm_x4(a[0][mt], cur + aoff + (uint32_t)(mt * 16) * TSTRIDE);
            ldsm_x4(r1, cur + boff + 16 * TSTRIDE);
            bf[0][0][0] = r0[0]; bf[0][0][1] = r0[2];
            bf[0][1][0] = r0[1]; bf[0][1][1] = r0[3];
            bf[0][2][0] = r1[0]; bf[0][2][1] = r1[2];
            bf[0][3][0] = r1[1]; bf[0][3][1] = r1[3];
        }

        // issue next-stage cp.async under the first fragment loads
        if (it + 2 < NITER) {
            stage_all(fut, bm, bn, (it + 2) * KC);
        } else {
            asm volatile("cp.async.commit_group;" ::: "memory");  // keep counts
        }

        #pragma unroll
        for (int kk = 0; kk < 4; ++kk) {
            const int cb = kk & 1, nb = cb ^ 1;

            if (kk < 3) {   // prefetch kk+1 fragments under this kk's MMAs
                const uint32_t kb = (uint32_t)((kk + 1) * 32);
                uint32_t r0[4], r1[4];
                ldsm_x4(r0, cur + boff + kb);
                #pragma unroll
                for (int mt = 0; mt < 4; ++mt)
                    ldsm_x4(a[nb][mt], cur + aoff + (uint32_t)(mt * 16) * TSTRIDE + kb);
                ldsm_x4(r1, cur + boff + 16 * TSTRIDE + kb);
                bf[nb][0][0] = r0[0]; bf[nb][0][1] = r0[2];
                bf[nb][1][0] = r0[1]; bf[nb][1][1] = r0[3];
                bf[nb][2][0] = r1[0]; bf[nb][2][1] = r1[2];
                bf[nb][3][0] = r1[1]; bf[nb][3][1] = r1[3];
            }

            #pragma unroll
            for (int mt = 0; mt < 4; ++mt)
                #pragma unroll
                for (int nt = 0; nt < 4; ++nt)
                    mma16816(acc[mt][nt], a[cb][mt], bf[cb][nt]);
        }

        const uint32_t top = sbase + 2 * STAGE_B;
        cur = (cur == top) ? sbase : cur + STAGE_B;
        fut = (fut == top) ? sbase : fut + STAGE_B;
    }

    // Epilogue: direct float2 stores
    const int er = lane >> 2;
    const int ec = (lane & 3) * 2;
    #pragma unroll
    for (int mt = 0; mt < 4; ++mt) {
        const int row = bm + wm * 64 + mt * 16 + er;
        #pragma unroll
        for (int nt = 0; nt < 4; ++nt) {
            const int col = bn + wn * 32 + nt * 8 + ec;
            *(float2*)(C + (size_t)row * O_ + col) =
                make_float2(acc[mt][nt][0], acc[mt][nt][1]);
            *(float2*)(C + (size_t)(row + 8) * O_ + col) =
                make_float2(acc[mt][nt][2], acc[mt][nt][3]);
        }
    }
}

// ---------------------------------------------------------------------------
extern "C" void kernel_launch(void* const* d_in, const int* in_sizes, int n_in,
                              void* d_out, int out_size)
{
    const float*         x      = (const float*)d_in[0];
    const float*         w      = (const float*)d_in[1];
    const float*         wn     = (const float*)d_in[2];
    const int*           perm   = (const int*)d_in[3];
    const unsigned char* stored = (const unsigned char*)d_in[4];
    const int*           pb     = (const int*)d_in[5];
    float*               out    = (float*)d_out;

    (void)in_sizes; (void)n_in; (void)out_size;

    static bool attr_set = false;
    if (!attr_set) {
        cudaFuncSetAttribute(gemm_kernel, cudaFuncAttributeMaxDynamicSharedMemorySize,
                             SMEM_GEMM);
        attr_set = true;
    }

    mean_p1<<<dim3(32, 8), 128>>>(x, pb);                      // 0
    rank_kernel<<<32, 512>>>(perm, pb, stored);                // 1
    split_kernel<<<XBLKS_ + WBLKS_, 256>>>(x, w, wn, stored);  // 2
    dim3 grid(O_ / 128, M_ / 128);
    gemm_kernel<<<grid, 256, SMEM_GEMM>>>(out);                // 3 <- ncu slot
}